// round 2
// baseline (speedup 1.0000x reference)
#include <cuda_runtime.h>
#include <math_constants.h>
#include <cstdint>
#include <cstddef>

#define B_ 32
#define N_ 1024
#define H_ 256

// Scratch for Q/K/V projections (device globals: allowed, no runtime alloc)
__device__ float g_q[B_ * N_ * H_];
__device__ float g_k[B_ * N_ * H_];
__device__ float g_v[B_ * N_ * H_];

// ---------------------------------------------------------------------------
// Kernel A: QKV projection. out = feats @ W + b for W in {Wq, Wk, Wv}.
// M = B*N = 32768, K = 256, N = 256. Tile 64x64, k-tile 32, 4x4 microtile.
// grid = (512, 4, 3), block = 256.
// ---------------------------------------------------------------------------
__global__ __launch_bounds__(256, 1)
void qkv_kernel(const float* __restrict__ feats,
                const float* __restrict__ Wq, const float* __restrict__ bq,
                const float* __restrict__ Wk, const float* __restrict__ bk,
                const float* __restrict__ Wv, const float* __restrict__ bv)
{
    __shared__ __align__(16) float As[64][36];   // padded (36) to break write conflicts
    __shared__ __align__(16) float Bs[32][68];   // padded (68)

    const float* W;
    const float* bias;
    float* out;
    if (blockIdx.z == 0)      { W = Wq; bias = bq; out = g_q; }
    else if (blockIdx.z == 1) { W = Wk; bias = bk; out = g_k; }
    else                      { W = Wv; bias = bv; out = g_v; }

    const int tid = threadIdx.x;
    const int ty = tid >> 4;       // 0..15 (4 rows each)
    const int tx = tid & 15;       // 0..15 (4 cols each)
    const int row0 = blockIdx.x * 64;
    const int col0 = blockIdx.y * 64;

    float acc[4][4];
#pragma unroll
    for (int i = 0; i < 4; i++)
#pragma unroll
        for (int j = 0; j < 4; j++) acc[i][j] = 0.0f;

    for (int kt = 0; kt < H_; kt += 32) {
        // Load A tile 64x32 (coalesced float4)
        {
            int idx = tid;
#pragma unroll
            for (int p = 0; p < 2; p++) {
                int r  = idx >> 3;
                int c4 = (idx & 7) * 4;
                float4 v = *(const float4*)(feats + (size_t)(row0 + r) * H_ + kt + c4);
                *(float4*)&As[r][c4] = v;
                idx += 256;
            }
        }
        // Load B tile 32x64 (coalesced float4)
        {
            int idx = tid;
#pragma unroll
            for (int p = 0; p < 2; p++) {
                int r  = idx >> 4;
                int c4 = (idx & 15) * 4;
                float4 v = *(const float4*)(W + (size_t)(kt + r) * H_ + col0 + c4);
                *(float4*)&Bs[r][c4] = v;
                idx += 256;
            }
        }
        __syncthreads();

#pragma unroll
        for (int k = 0; k < 32; k++) {
            float4 bv4 = *(const float4*)&Bs[k][tx * 4];
#pragma unroll
            for (int i = 0; i < 4; i++) {
                float a = As[ty * 4 + i][k];
                acc[i][0] = fmaf(a, bv4.x, acc[i][0]);
                acc[i][1] = fmaf(a, bv4.y, acc[i][1]);
                acc[i][2] = fmaf(a, bv4.z, acc[i][2]);
                acc[i][3] = fmaf(a, bv4.w, acc[i][3]);
            }
        }
        __syncthreads();
    }

    float4 bb = *(const float4*)(bias + col0 + tx * 4);
#pragma unroll
    for (int i = 0; i < 4; i++) {
        float4 o;
        o.x = acc[i][0] + bb.x;
        o.y = acc[i][1] + bb.y;
        o.z = acc[i][2] + bb.z;
        o.w = acc[i][3] + bb.w;
        *(float4*)(out + (size_t)(row0 + ty * 4 + i) * H_ + col0 + tx * 4) = o;
    }
}

// ---------------------------------------------------------------------------
// Kernel B: fused attention + LayerNorm + ReLU.
// One block = (batch b, 64-query tile). Flash-style online softmax over 16
// key tiles of 64. 4x4 S microtile; O = 64 regs/thread (4 rows x 16 cols).
// ---------------------------------------------------------------------------

__device__ __forceinline__ float rmax16(float v) {
#pragma unroll
    for (int off = 8; off > 0; off >>= 1)
        v = fmaxf(v, __shfl_xor_sync(0xffffffffu, v, off));
    return v;
}
__device__ __forceinline__ float rsum16(float v) {
#pragma unroll
    for (int off = 8; off > 0; off >>= 1)
        v += __shfl_xor_sync(0xffffffffu, v, off);
    return v;
}

// smem layout (floats): Qs 16384 | Kt 16384 | Vs 16384 | Ps 4096 | kmf 1024 |
//                       mqf 64 | gsm 256 | bsm 256  = 54848 floats = 219392 B
#define SMEM_ATTN_BYTES (54848 * 4)

__global__ __launch_bounds__(256, 1)
void attn_kernel(const int* __restrict__ masks,
                 const float* __restrict__ gamma,
                 const float* __restrict__ beta,
                 float* __restrict__ out)
{
    extern __shared__ float sm[];
    float* Qs  = sm;                  // [64][256] row-major, pre-scaled by 1/16
    float* Kt  = Qs + 64 * H_;        // [256][64] transposed (d-major)
    float* Vs  = Kt + H_ * 64;        // [64][256] row-major
    float* Ps  = Vs + 64 * H_;        // [64][64]
    float* kmf = Ps + 64 * 64;        // [1024] key masks as float
    float* mqf = kmf + N_;            // [64] query masks
    float* gsm = mqf + 64;            // [256] gamma
    float* bsm = gsm + H_;            // [256] beta

    const int tid = threadIdx.x;
    const int b  = blockIdx.y;
    const int q0 = blockIdx.x * 64;
    const int ty = tid >> 4;
    const int tx = tid & 15;
    const float scale = 0.0625f;      // 1/sqrt(256)

    const size_t qbase = ((size_t)b * N_ + q0) * H_;

    // Load Q tile (scaled), masks, gamma/beta
    for (int idx = tid; idx < 64 * 64; idx += 256) {
        int r = idx >> 6;
        int c = (idx & 63) * 4;
        float4 v = *(const float4*)(g_q + qbase + r * H_ + c);
        v.x *= scale; v.y *= scale; v.z *= scale; v.w *= scale;
        *(float4*)(Qs + r * H_ + c) = v;
    }
    for (int idx = tid; idx < N_; idx += 256)
        kmf[idx] = masks[b * N_ + idx] ? 1.0f : 0.0f;
    if (tid < 64) mqf[tid] = masks[b * N_ + q0 + tid] ? 1.0f : 0.0f;
    if (tid < H_) { gsm[tid] = gamma[tid]; bsm[tid] = beta[tid]; }
    __syncthreads();

    float o[4][16];
#pragma unroll
    for (int i = 0; i < 4; i++)
#pragma unroll
        for (int c = 0; c < 16; c++) o[i][c] = 0.0f;

    float mrow[4], lrow[4], mqr[4];
#pragma unroll
    for (int i = 0; i < 4; i++) {
        mrow[i] = -CUDART_INF_F;
        lrow[i] = 0.0f;
        mqr[i]  = mqf[ty * 4 + i];
    }

    for (int kt0 = 0; kt0 < N_; kt0 += 64) {
        const size_t kbase = ((size_t)b * N_ + kt0) * H_;

        // Load K tile transposed: Kt[d][key]
        {
            int key = tid >> 2;
            int dq  = (tid & 3) * 4;
#pragma unroll
            for (int i2 = 0; i2 < 16; i2++) {
                int d = dq + i2 * 16;
                float4 v = *(const float4*)(g_k + kbase + key * H_ + d);
                Kt[(d + 0) * 64 + key] = v.x;
                Kt[(d + 1) * 64 + key] = v.y;
                Kt[(d + 2) * 64 + key] = v.z;
                Kt[(d + 3) * 64 + key] = v.w;
            }
        }
        // Load V tile row-major
        for (int idx = tid; idx < 64 * 64; idx += 256) {
            int r = idx >> 6;
            int c = (idx & 63) * 4;
            *(float4*)(Vs + r * H_ + c) = *(const float4*)(g_v + kbase + r * H_ + c);
        }
        __syncthreads();

        // S = Qs @ Kt  (64x64, K=256)
        float s[4][4];
#pragma unroll
        for (int i = 0; i < 4; i++)
#pragma unroll
            for (int j = 0; j < 4; j++) s[i][j] = 0.0f;

#pragma unroll 4
        for (int d = 0; d < H_; d += 4) {
            float4 a[4];
#pragma unroll
            for (int i = 0; i < 4; i++)
                a[i] = *(const float4*)(Qs + (ty * 4 + i) * H_ + d);
#pragma unroll
            for (int dd = 0; dd < 4; dd++) {
                float4 bv4 = *(const float4*)(Kt + (d + dd) * 64 + tx * 4);
#pragma unroll
                for (int i = 0; i < 4; i++) {
                    float av = ((const float*)&a[i])[dd];
                    s[i][0] = fmaf(av, bv4.x, s[i][0]);
                    s[i][1] = fmaf(av, bv4.y, s[i][1]);
                    s[i][2] = fmaf(av, bv4.z, s[i][2]);
                    s[i][3] = fmaf(av, bv4.w, s[i][3]);
                }
            }
        }

        // Additive mask: +1 where both masks set, -1e5 otherwise (exact ref semantics)
        float kmv[4];
#pragma unroll
        for (int j = 0; j < 4; j++) kmv[j] = kmf[kt0 + tx * 4 + j];
#pragma unroll
        for (int i = 0; i < 4; i++)
#pragma unroll
            for (int j = 0; j < 4; j++)
                s[i][j] += (mqr[i] * kmv[j] > 0.5f) ? 1.0f : -100000.0f;

        // Online softmax update + write P
#pragma unroll
        for (int i = 0; i < 4; i++) {
            float tm = fmaxf(fmaxf(s[i][0], s[i][1]), fmaxf(s[i][2], s[i][3]));
            tm = rmax16(tm);
            float nm  = fmaxf(mrow[i], tm);
            float fac = __expf(mrow[i] - nm);   // first tile: exp(-inf) = 0
            float p0 = __expf(s[i][0] - nm);
            float p1 = __expf(s[i][1] - nm);
            float p2 = __expf(s[i][2] - nm);
            float p3 = __expf(s[i][3] - nm);
            float ps = rsum16(p0 + p1 + p2 + p3);
            lrow[i] = lrow[i] * fac + ps;
            mrow[i] = nm;
#pragma unroll
            for (int c = 0; c < 16; c++) o[i][c] *= fac;
            float4 pv = make_float4(p0, p1, p2, p3);
            *(float4*)(Ps + (ty * 4 + i) * 64 + tx * 4) = pv;
        }
        __syncthreads();

        // O += P @ V  (64x256, K=64)
#pragma unroll
        for (int dc = 0; dc < 4; dc++) {
#pragma unroll 4
            for (int k = 0; k < 64; k += 4) {
                float4 a[4];
#pragma unroll
                for (int i = 0; i < 4; i++)
                    a[i] = *(const float4*)(Ps + (ty * 4 + i) * 64 + k);
#pragma unroll
                for (int kk = 0; kk < 4; kk++) {
                    float4 bv4 = *(const float4*)(Vs + (k + kk) * H_ + dc * 64 + tx * 4);
#pragma unroll
                    for (int i = 0; i < 4; i++) {
                        float av = ((const float*)&a[i])[kk];
                        o[i][dc * 4 + 0] = fmaf(av, bv4.x, o[i][dc * 4 + 0]);
                        o[i][dc * 4 + 1] = fmaf(av, bv4.y, o[i][dc * 4 + 1]);
                        o[i][dc * 4 + 2] = fmaf(av, bv4.z, o[i][dc * 4 + 2]);
                        o[i][dc * 4 + 3] = fmaf(av, bv4.w, o[i][dc * 4 + 3]);
                    }
                }
            }
        }
        __syncthreads();
    }

    // Epilogue: normalize by l, LayerNorm over H, ReLU, store
#pragma unroll
    for (int i = 0; i < 4; i++) {
        float inv = 1.0f / lrow[i];
        float sum = 0.0f;
#pragma unroll
        for (int c = 0; c < 16; c++) { o[i][c] *= inv; sum += o[i][c]; }
        sum = rsum16(sum);
        float mu = sum * (1.0f / H_);
        float vs = 0.0f;
#pragma unroll
        for (int c = 0; c < 16; c++) { float d = o[i][c] - mu; vs = fmaf(d, d, vs); }
        vs = rsum16(vs);
        float rstd = rsqrtf(vs * (1.0f / H_) + 1e-5f);

        size_t obase = qbase + (size_t)(ty * 4 + i) * H_;
#pragma unroll
        for (int dc = 0; dc < 4; dc++) {
            int col = dc * 64 + tx * 4;
            float4 y;
            y.x = fmaxf((o[i][dc * 4 + 0] - mu) * rstd * gsm[col + 0] + bsm[col + 0], 0.0f);
            y.y = fmaxf((o[i][dc * 4 + 1] - mu) * rstd * gsm[col + 1] + bsm[col + 1], 0.0f);
            y.z = fmaxf((o[i][dc * 4 + 2] - mu) * rstd * gsm[col + 2] + bsm[col + 2], 0.0f);
            y.w = fmaxf((o[i][dc * 4 + 3] - mu) * rstd * gsm[col + 3] + bsm[col + 3], 0.0f);
            *(float4*)(out + obase + col) = y;
        }
    }
}

// ---------------------------------------------------------------------------
// Launch
// ---------------------------------------------------------------------------
extern "C" void kernel_launch(void* const* d_in, const int* in_sizes, int n_in,
                              void* d_out, int out_size)
{
    const float* feats = (const float*)d_in[0];
    const int*   masks = (const int*)d_in[1];
    const float* Wq    = (const float*)d_in[2];
    const float* bq    = (const float*)d_in[3];
    const float* Wk    = (const float*)d_in[4];
    const float* bk    = (const float*)d_in[5];
    const float* Wv    = (const float*)d_in[6];
    const float* bv    = (const float*)d_in[7];
    const float* gamma = (const float*)d_in[8];
    const float* beta  = (const float*)d_in[9];
    float* out = (float*)d_out;

    dim3 gA((B_ * N_) / 64, H_ / 64, 3);
    qkv_kernel<<<gA, 256>>>(feats, Wq, bq, Wk, bk, Wv, bv);

    cudaFuncSetAttribute(attn_kernel,
                         cudaFuncAttributeMaxDynamicSharedMemorySize,
                         SMEM_ATTN_BYTES);
    dim3 gB(N_ / 64, B_);
    attn_kernel<<<gB, 256, SMEM_ATTN_BYTES>>>(masks, gamma, beta, out);
}

// round 12
// speedup vs baseline: 1.7796x; 1.7796x over previous
#include <cuda_runtime.h>
#include <cuda_fp16.h>
#include <cstdint>
#include <cstddef>

#define B_ 32
#define N_ 1024
#define H_ 256
#define QT 128

// Q,K,V all stored scaled by x16 (keeps fp16 lo-planes out of subnormal range).
// S_mma = 256*(q.k); softmax applies 1/4096 then shift. V x16 cancels in LayerNorm.
#define SSCALE 2.44140625e-4f   // 1/4096

__device__ __half g_qhi[B_*N_*H_], g_qlo[B_*N_*H_];
__device__ __half g_khi[B_*N_*H_], g_klo[B_*N_*H_];
__device__ __half g_vhi[B_*N_*H_], g_vlo[B_*N_*H_];

// ---------------- helpers ----------------
__device__ __forceinline__ uint32_t smem_u32(const void* p) {
    uint32_t a;
    asm("{ .reg .u64 t; cvta.to.shared.u64 t, %1; cvt.u32.u64 %0, t; }" : "=r"(a) : "l"(p));
    return a;
}
__device__ __forceinline__ void ldsm4(uint32_t* r, uint32_t a) {
    asm volatile("ldmatrix.sync.aligned.m8n8.x4.shared.b16 {%0,%1,%2,%3}, [%4];"
        : "=r"(r[0]), "=r"(r[1]), "=r"(r[2]), "=r"(r[3]) : "r"(a));
}
__device__ __forceinline__ void ldsm4t(uint32_t* r, uint32_t a) {
    asm volatile("ldmatrix.sync.aligned.m8n8.x4.trans.shared.b16 {%0,%1,%2,%3}, [%4];"
        : "=r"(r[0]), "=r"(r[1]), "=r"(r[2]), "=r"(r[3]) : "r"(a));
}
__device__ __forceinline__ void mma16816(float* d, const uint32_t* a, const uint32_t* b) {
    asm volatile("mma.sync.aligned.m16n8k16.row.col.f32.f16.f16.f32 "
        "{%0,%1,%2,%3}, {%4,%5,%6,%7}, {%8,%9}, {%0,%1,%2,%3};"
        : "+f"(d[0]), "+f"(d[1]), "+f"(d[2]), "+f"(d[3])
        : "r"(a[0]), "r"(a[1]), "r"(a[2]), "r"(a[3]), "r"(b[0]), "r"(b[1]));
}
__device__ __forceinline__ uint32_t packh2(float a, float b) {
    __half2 t = __floats2half2_rn(a, b);   // .x = a (low), .y = b (high)
    return *(uint32_t*)&t;
}

// Softmax numerator for one element, replicating the REFERENCE's fp32
// rounding semantics:
//  - valid row + valid key:   ref adds +1.0 then softmaxes  -> exp(s - 5)
//  - valid row + invalid key: ref adds -1e5 -> exact 0 after max-subtract
//  - invalid row (all keys):  ref adds -1e5 in fp32, which QUANTIZES the
//    score to ulp(1e5)=2^-7 before softmax. Replicate: (s-1e5)+1e5 exactly.
__device__ __forceinline__ float softp(float smma, bool rowvalid, bool keyvalid) {
    float s = __fmul_rn(smma, SSCALE);
    if (rowvalid) {
        return keyvalid ? __expf(__fadd_rn(s, -5.0f)) : 0.0f;
    } else {
        float t  = __fadd_rn(s, -100000.0f);   // quantize like reference
        float sq = __fadd_rn(t,  100000.0f);   // exact recovery of grid value
        return __expf(__fadd_rn(sq, -6.0f));
    }
}

// ---------------------------------------------------------------------------
// Kernel A: QKV projection -> fp16 hi/lo, all scaled x16.
// ---------------------------------------------------------------------------
__global__ __launch_bounds__(256, 1)
void qkv_kernel(const float* __restrict__ feats,
                const float* __restrict__ Wq, const float* __restrict__ bq,
                const float* __restrict__ Wk, const float* __restrict__ bk,
                const float* __restrict__ Wv, const float* __restrict__ bv)
{
    __shared__ __align__(16) float As[64][36];
    __shared__ __align__(16) float Bs[32][68];

    const float* W; const float* bias;
    __half *ohi, *olo;
    if (blockIdx.z == 0)      { W = Wq; bias = bq; ohi = g_qhi; olo = g_qlo; }
    else if (blockIdx.z == 1) { W = Wk; bias = bk; ohi = g_khi; olo = g_klo; }
    else                      { W = Wv; bias = bv; ohi = g_vhi; olo = g_vlo; }
    const float pre = 16.0f;

    const int tid = threadIdx.x, ty = tid >> 4, tx = tid & 15;
    const int row0 = blockIdx.x * 64, col0 = blockIdx.y * 64;

    float acc[4][4];
#pragma unroll
    for (int i = 0; i < 4; i++)
#pragma unroll
        for (int j = 0; j < 4; j++) acc[i][j] = 0.0f;

    for (int kt = 0; kt < H_; kt += 32) {
        int idx = tid;
#pragma unroll
        for (int p = 0; p < 2; p++) {
            int r = idx >> 3, c4 = (idx & 7) * 4;
            *(float4*)&As[r][c4] = *(const float4*)(feats + (size_t)(row0+r)*H_ + kt + c4);
            int r2 = idx >> 4, c42 = (idx & 15) * 4;
            *(float4*)&Bs[r2][c42] = *(const float4*)(W + (size_t)(kt+r2)*H_ + col0 + c42);
            idx += 256;
        }
        __syncthreads();
#pragma unroll
        for (int k = 0; k < 32; k++) {
            float4 b4 = *(const float4*)&Bs[k][tx*4];
#pragma unroll
            for (int i = 0; i < 4; i++) {
                float a = As[ty*4+i][k];
                acc[i][0] = fmaf(a, b4.x, acc[i][0]); acc[i][1] = fmaf(a, b4.y, acc[i][1]);
                acc[i][2] = fmaf(a, b4.z, acc[i][2]); acc[i][3] = fmaf(a, b4.w, acc[i][3]);
            }
        }
        __syncthreads();
    }

    float4 bb = *(const float4*)(bias + col0 + tx*4);
#pragma unroll
    for (int i = 0; i < 4; i++) {
        float v[4] = { (acc[i][0]+bb.x)*pre, (acc[i][1]+bb.y)*pre,
                       (acc[i][2]+bb.z)*pre, (acc[i][3]+bb.w)*pre };
        size_t base = (size_t)(row0+ty*4+i)*H_ + col0 + tx*4;
        __half hv[4], lv[4];
#pragma unroll
        for (int j = 0; j < 4; j++) {
            hv[j] = __float2half(v[j]);
            lv[j] = __float2half(v[j] - __half2float(hv[j]));
        }
        *(uint2*)(ohi + base) = *(uint2*)hv;
        *(uint2*)(olo + base) = *(uint2*)lv;
    }
}

// ---------------------------------------------------------------------------
// Kernel B: FA2-style mma.sync fp16x3 attention + LayerNorm + ReLU.
// smem: Qhi | Qlo | KVhi | KVlo | maskbits | gamma | beta   (pitch 528B rows)
// ---------------------------------------------------------------------------
#define PITCH 528
#define SQHI  0
#define SQLO  67584
#define SKV0  135168
#define SKV1  168960
#define SMASK 202752
#define SGAM  202880
#define SBET  203904
#define SMEM_ATTN 204928

__global__ __launch_bounds__(256, 1)
void attn_mma_kernel(const int* __restrict__ masks,
                     const float* __restrict__ gamma,
                     const float* __restrict__ beta,
                     float* __restrict__ out)
{
    extern __shared__ char smc[];
    const uint32_t sb = smem_u32(smc);
    const int tid = threadIdx.x, w = tid >> 5, l = tid & 31;
    const int b = blockIdx.y, q0 = blockIdx.x * QT;

    // ---- stage Q hi/lo, mask bits, gamma/beta ----
    {
        const size_t qb = (size_t)(b*N_ + q0) * H_;
        for (int idx = tid; idx < QT*32; idx += 256) {
            int r = idx >> 5, c = idx & 31;
            uint32_t so = (uint32_t)r*PITCH + (uint32_t)c*16;
            *(uint4*)(smc + SQHI + so) = *(const uint4*)(g_qhi + qb + (size_t)r*H_ + c*8);
            *(uint4*)(smc + SQLO + so) = *(const uint4*)(g_qlo + qb + (size_t)r*H_ + c*8);
        }
        if (tid < 32) {
            uint32_t wbits = 0;
            for (int j = 0; j < 32; j++) wbits |= (masks[b*N_ + tid*32 + j] ? 1u : 0u) << j;
            ((uint32_t*)(smc + SMASK))[tid] = wbits;
        }
        for (int idx = tid; idx < H_; idx += 256) {
            ((float*)(smc + SGAM))[idx] = gamma[idx];
            ((float*)(smc + SBET))[idx] = beta[idx];
        }
    }

    const int r0 = 16*w + (l >> 2), r1 = r0 + 8;
    const bool mq0 = masks[b*N_ + q0 + r0] != 0, mq1 = masks[b*N_ + q0 + r1] != 0;

    float O[32][4];
#pragma unroll
    for (int t = 0; t < 32; t++)
#pragma unroll
        for (int j = 0; j < 4; j++) O[t][j] = 0.0f;
    float ls0 = 0.0f, ls1 = 0.0f;

    const int c0 = 2*(l & 3);
    // ldmatrix lane-address components (bytes)
    const uint32_t aoff = (uint32_t)(16*w + (l & 15))*PITCH + (uint32_t)(l >> 4)*16; // A (Q)
    const uint32_t krow = (uint32_t)((l & 7) + ((l >> 4) << 3));                      // K rows (n)
    const uint32_t kcol = (uint32_t)(((l >> 3) & 1))*16;                              // K col byte
    const uint32_t vrow = (uint32_t)((l & 7) + (((l >> 3) & 1) << 3));                // V rows (k)
    const uint32_t vcol = (uint32_t)(l >> 4)*16;                                      // V col byte

    __syncthreads();

    for (int it = 0; it < 16; it++) {
        // ---- load K tile hi/lo ----
        {
            const size_t kb = (size_t)(b*N_ + it*64) * H_;
            for (int idx = tid; idx < 64*32; idx += 256) {
                int r = idx >> 5, c = idx & 31;
                uint32_t so = (uint32_t)r*PITCH + (uint32_t)c*16;
                *(uint4*)(smc + SKV0 + so) = *(const uint4*)(g_khi + kb + (size_t)r*H_ + c*8);
                *(uint4*)(smc + SKV1 + so) = *(const uint4*)(g_klo + kb + (size_t)r*H_ + c*8);
            }
        }
        __syncthreads();

        // ---- S = Q·K^T (16x64 per warp), fp16x3 ----
        float S[8][4];
#pragma unroll
        for (int t = 0; t < 8; t++)
#pragma unroll
            for (int j = 0; j < 4; j++) S[t][j] = 0.0f;

#pragma unroll 4
        for (int kc = 0; kc < 16; kc++) {
            uint32_t Ah[4], Al[4];
            uint32_t ao = aoff + (uint32_t)kc*32;
            ldsm4(Ah, sb + SQHI + ao);
            ldsm4(Al, sb + SQLO + ao);
#pragma unroll
            for (int np = 0; np < 4; np++) {
                uint32_t Bh[4], Bl[4];
                uint32_t ko = (krow + np*16)*PITCH + (uint32_t)kc*32 + kcol;
                ldsm4(Bh, sb + SKV0 + ko);
                ldsm4(Bl, sb + SKV1 + ko);
                mma16816(S[2*np],   Ah, Bh);     mma16816(S[2*np],   Ah, Bl);
                mma16816(S[2*np],   Al, Bh);
                mma16816(S[2*np+1], Ah, Bh+2);   mma16816(S[2*np+1], Ah, Bl+2);
                mma16816(S[2*np+1], Al, Bh+2);
            }
        }

        // ---- softmax (reference-exact rounding semantics) -> P fragments ----
        const uint32_t w0 = ((uint32_t*)(smc + SMASK))[it*2];
        const uint32_t w1 = ((uint32_t*)(smc + SMASK))[it*2 + 1];
        uint32_t Phi[4][4], Plo[4][4];
#pragma unroll
        for (int j = 0; j < 8; j++) {
            int kidx = j*8 + c0;               // key index within tile (0..63)
            uint32_t mw = (j < 4) ? w0 : w1;
            int sh = kidx & 31;
            bool kb0 = (mw >> sh) & 1, kb1 = (mw >> (sh+1)) & 1;
            float p0 = softp(S[j][0], mq0, kb0);
            float p1 = softp(S[j][1], mq0, kb1);
            float p2 = softp(S[j][2], mq1, kb0);
            float p3 = softp(S[j][3], mq1, kb1);
            ls0 += p0 + p1; ls1 += p2 + p3;
            __half h0 = __float2half(p0), h1 = __float2half(p1);
            __half h2 = __float2half(p2), h3 = __float2half(p3);
            float l0 = p0 - __half2float(h0), l1 = p1 - __half2float(h1);
            float l2 = p2 - __half2float(h2), l3 = p3 - __half2float(h3);
            int kc = j >> 1, hi = (j & 1) ? 2 : 0;
            Phi[kc][hi+0] = ((uint32_t)__half_as_ushort(h0)) | ((uint32_t)__half_as_ushort(h1) << 16);
            Phi[kc][hi+1] = ((uint32_t)__half_as_ushort(h2)) | ((uint32_t)__half_as_ushort(h3) << 16);
            Plo[kc][hi+0] = packh2(l0, l1);
            Plo[kc][hi+1] = packh2(l2, l3);
        }
        __syncthreads();   // all warps done reading K

        // ---- load V tile hi/lo (overwrites K buffer) ----
        {
            const size_t vb = (size_t)(b*N_ + it*64) * H_;
            for (int idx = tid; idx < 64*32; idx += 256) {
                int r = idx >> 5, c = idx & 31;
                uint32_t so = (uint32_t)r*PITCH + (uint32_t)c*16;
                *(uint4*)(smc + SKV0 + so) = *(const uint4*)(g_vhi + vb + (size_t)r*H_ + c*8);
                *(uint4*)(smc + SKV1 + so) = *(const uint4*)(g_vlo + vb + (size_t)r*H_ + c*8);
            }
        }
        __syncthreads();

        // ---- O += P·V (16x256 per warp), fp16x3 ----
#pragma unroll
        for (int kc = 0; kc < 4; kc++) {
#pragma unroll
            for (int np = 0; np < 16; np++) {
                uint32_t Bh[4], Bl[4];
                uint32_t vo = (vrow + kc*16)*PITCH + (uint32_t)np*32 + vcol;
                ldsm4t(Bh, sb + SKV0 + vo);
                ldsm4t(Bl, sb + SKV1 + vo);
                mma16816(O[2*np],   Phi[kc], Bh);     mma16816(O[2*np],   Phi[kc], Bl);
                mma16816(O[2*np],   Plo[kc], Bh);
                mma16816(O[2*np+1], Phi[kc], Bh+2);   mma16816(O[2*np+1], Phi[kc], Bl+2);
                mma16816(O[2*np+1], Plo[kc], Bh+2);
            }
        }
        __syncthreads();   // all warps done reading V before next K load
    }

    // ---- epilogue: /l, LayerNorm (scale-invariant to V x16), ReLU, store ----
    ls0 += __shfl_xor_sync(0xffffffffu, ls0, 1); ls0 += __shfl_xor_sync(0xffffffffu, ls0, 2);
    ls1 += __shfl_xor_sync(0xffffffffu, ls1, 1); ls1 += __shfl_xor_sync(0xffffffffu, ls1, 2);
    const float inv0 = 1.0f / ls0, inv1 = 1.0f / ls1;

    float s0 = 0.0f, q0s = 0.0f, s1 = 0.0f, q1s = 0.0f;
#pragma unroll
    for (int t = 0; t < 32; t++) {
        float v0 = O[t][0]*inv0, v1 = O[t][1]*inv0;
        float v2 = O[t][2]*inv1, v3 = O[t][3]*inv1;
        s0 += v0 + v1; q0s = fmaf(v0,v0,fmaf(v1,v1,q0s));
        s1 += v2 + v3; q1s = fmaf(v2,v2,fmaf(v3,v3,q1s));
    }
    s0 += __shfl_xor_sync(0xffffffffu, s0, 1); s0 += __shfl_xor_sync(0xffffffffu, s0, 2);
    q0s += __shfl_xor_sync(0xffffffffu, q0s, 1); q0s += __shfl_xor_sync(0xffffffffu, q0s, 2);
    s1 += __shfl_xor_sync(0xffffffffu, s1, 1); s1 += __shfl_xor_sync(0xffffffffu, s1, 2);
    q1s += __shfl_xor_sync(0xffffffffu, q1s, 1); q1s += __shfl_xor_sync(0xffffffffu, q1s, 2);

    // O*inv is 16x the true attention output. Normalizing the x16 data with
    // its own mean/rstd yields EXACTLY the normalized true output:
    // (16o - 16mu)*rsqrt(256var + 256eps) = (o - mu)*rsqrt(var + eps).
    // eps scales x256 to match the x256 variance; NO post factor.
    const float mu0 = s0 * (1.0f/H_), mu1 = s1 * (1.0f/H_);
    const float rstd0 = rsqrtf(fmaxf(q0s*(1.0f/H_) - mu0*mu0, 0.0f) + 1e-5f*256.0f);
    const float rstd1 = rsqrtf(fmaxf(q1s*(1.0f/H_) - mu1*mu1, 0.0f) + 1e-5f*256.0f);

    const float* gsm = (const float*)(smc + SGAM);
    const float* bsm = (const float*)(smc + SBET);
    const size_t ob0 = (size_t)(b*N_ + q0 + r0) * H_;
    const size_t ob1 = (size_t)(b*N_ + q0 + r1) * H_;
#pragma unroll
    for (int t = 0; t < 32; t++) {
        int col = t*8 + c0;
        float2 y0, y1;
        y0.x = fmaxf((O[t][0]*inv0 - mu0)*rstd0*gsm[col]   + bsm[col],   0.0f);
        y0.y = fmaxf((O[t][1]*inv0 - mu0)*rstd0*gsm[col+1] + bsm[col+1], 0.0f);
        y1.x = fmaxf((O[t][2]*inv1 - mu1)*rstd1*gsm[col]   + bsm[col],   0.0f);
        y1.y = fmaxf((O[t][3]*inv1 - mu1)*rstd1*gsm[col+1] + bsm[col+1], 0.0f);
        *(float2*)(out + ob0 + col) = y0;
        *(float2*)(out + ob1 + col) = y1;
    }
}

// ---------------------------------------------------------------------------
extern "C" void kernel_launch(void* const* d_in, const int* in_sizes, int n_in,
                              void* d_out, int out_size)
{
    const float* feats = (const float*)d_in[0];
    const int*   masks = (const int*)d_in[1];
    const float* Wq = (const float*)d_in[2];
    const float* bq = (const float*)d_in[3];
    const float* Wk = (const float*)d_in[4];
    const float* bk = (const float*)d_in[5];
    const float* Wv = (const float*)d_in[6];
    const float* bv = (const float*)d_in[7];
    const float* gamma = (const float*)d_in[8];
    const float* beta  = (const float*)d_in[9];
    float* out = (float*)d_out;

    dim3 gA((B_*N_)/64, H_/64, 3);
    qkv_kernel<<<gA, 256>>>(feats, Wq, bq, Wk, bk, Wv, bv);

    cudaFuncSetAttribute(attn_mma_kernel,
                         cudaFuncAttributeMaxDynamicSharedMemorySize,
                         SMEM_ATTN);
    dim3 gB(N_/QT, B_);
    attn_mma_kernel<<<gB, 256, SMEM_ATTN>>>(masks, gamma, beta, out);
}

// round 13
// speedup vs baseline: 2.3579x; 1.3250x over previous
#include <cuda_runtime.h>
#include <cuda_fp16.h>
#include <cstdint>
#include <cstddef>

#define B_ 32
#define N_ 1024
#define H_ 256
#define QT 128

// Q,K,V all scaled x16 (keeps fp16 planes out of subnormal range).
// S_mma = 256*(q.k); softmax applies 1/4096 then shift. V x16 cancels in LayerNorm.
#define SSCALE 2.44140625e-4f   // 1/4096

__device__ __half g_qhi[B_*N_*H_], g_qlo[B_*N_*H_];
__device__ __half g_khi[B_*N_*H_];
__device__ __half g_vhi[B_*N_*H_];

// ---------------- helpers ----------------
__device__ __forceinline__ uint32_t smem_u32(const void* p) {
    uint32_t a;
    asm("{ .reg .u64 t; cvta.to.shared.u64 t, %1; cvt.u32.u64 %0, t; }" : "=r"(a) : "l"(p));
    return a;
}
__device__ __forceinline__ void ldsm4(uint32_t* r, uint32_t a) {
    asm volatile("ldmatrix.sync.aligned.m8n8.x4.shared.b16 {%0,%1,%2,%3}, [%4];"
        : "=r"(r[0]), "=r"(r[1]), "=r"(r[2]), "=r"(r[3]) : "r"(a));
}
__device__ __forceinline__ void ldsm4t(uint32_t* r, uint32_t a) {
    asm volatile("ldmatrix.sync.aligned.m8n8.x4.trans.shared.b16 {%0,%1,%2,%3}, [%4];"
        : "=r"(r[0]), "=r"(r[1]), "=r"(r[2]), "=r"(r[3]) : "r"(a));
}
__device__ __forceinline__ void mma16816(float* d, const uint32_t* a, const uint32_t* b) {
    asm volatile("mma.sync.aligned.m16n8k16.row.col.f32.f16.f16.f32 "
        "{%0,%1,%2,%3}, {%4,%5,%6,%7}, {%8,%9}, {%0,%1,%2,%3};"
        : "+f"(d[0]), "+f"(d[1]), "+f"(d[2]), "+f"(d[3])
        : "r"(a[0]), "r"(a[1]), "r"(a[2]), "r"(a[3]), "r"(b[0]), "r"(b[1]));
}
__device__ __forceinline__ uint32_t packh2(float a, float b) {
    __half2 t = __floats2half2_rn(a, b);
    return *(uint32_t*)&t;
}
__device__ __forceinline__ void cpa16(uint32_t s, const void* g) {
    asm volatile("cp.async.cg.shared.global [%0], [%1], 16;" :: "r"(s), "l"(g));
}
#define CPA_COMMIT() asm volatile("cp.async.commit_group;" ::: "memory")
#define CPA_WAIT1()  asm volatile("cp.async.wait_group 1;" ::: "memory")

// Softmax numerator, replicating the REFERENCE's fp32 rounding semantics:
//  - valid row + valid key:   exp(s - 5)
//  - valid row + invalid key: exact 0
//  - invalid row: ref adds -1e5 in fp32 which QUANTIZES s to ulp(1e5)=2^-7.
__device__ __forceinline__ float softp(float smma, bool rowvalid, bool keyvalid) {
    float s = __fmul_rn(smma, SSCALE);
    if (rowvalid) {
        return keyvalid ? __expf(__fadd_rn(s, -5.0f)) : 0.0f;
    } else {
        float t  = __fadd_rn(s, -100000.0f);
        float sq = __fadd_rn(t,  100000.0f);
        return __expf(__fadd_rn(sq, -6.0f));
    }
}

// ---------------------------------------------------------------------------
// Kernel A: QKV projection -> fp16 (Q: hi+lo split; K,V: hi only), all x16.
// ---------------------------------------------------------------------------
__global__ __launch_bounds__(256, 1)
void qkv_kernel(const float* __restrict__ feats,
                const float* __restrict__ Wq, const float* __restrict__ bq,
                const float* __restrict__ Wk, const float* __restrict__ bk,
                const float* __restrict__ Wv, const float* __restrict__ bv)
{
    __shared__ __align__(16) float As[64][36];
    __shared__ __align__(16) float Bs[32][68];

    const float* W; const float* bias;
    __half* ohi;
    if (blockIdx.z == 0)      { W = Wq; bias = bq; ohi = g_qhi; }
    else if (blockIdx.z == 1) { W = Wk; bias = bk; ohi = g_khi; }
    else                      { W = Wv; bias = bv; ohi = g_vhi; }
    const bool wlo = (blockIdx.z == 0);
    const float pre = 16.0f;

    const int tid = threadIdx.x, ty = tid >> 4, tx = tid & 15;
    const int row0 = blockIdx.x * 64, col0 = blockIdx.y * 64;

    float acc[4][4];
#pragma unroll
    for (int i = 0; i < 4; i++)
#pragma unroll
        for (int j = 0; j < 4; j++) acc[i][j] = 0.0f;

    for (int kt = 0; kt < H_; kt += 32) {
        int idx = tid;
#pragma unroll
        for (int p = 0; p < 2; p++) {
            int r = idx >> 3, c4 = (idx & 7) * 4;
            *(float4*)&As[r][c4] = *(const float4*)(feats + (size_t)(row0+r)*H_ + kt + c4);
            int r2 = idx >> 4, c42 = (idx & 15) * 4;
            *(float4*)&Bs[r2][c42] = *(const float4*)(W + (size_t)(kt+r2)*H_ + col0 + c42);
            idx += 256;
        }
        __syncthreads();
#pragma unroll
        for (int k = 0; k < 32; k++) {
            float4 b4 = *(const float4*)&Bs[k][tx*4];
#pragma unroll
            for (int i = 0; i < 4; i++) {
                float a = As[ty*4+i][k];
                acc[i][0] = fmaf(a, b4.x, acc[i][0]); acc[i][1] = fmaf(a, b4.y, acc[i][1]);
                acc[i][2] = fmaf(a, b4.z, acc[i][2]); acc[i][3] = fmaf(a, b4.w, acc[i][3]);
            }
        }
        __syncthreads();
    }

    float4 bb = *(const float4*)(bias + col0 + tx*4);
#pragma unroll
    for (int i = 0; i < 4; i++) {
        float v[4] = { (acc[i][0]+bb.x)*pre, (acc[i][1]+bb.y)*pre,
                       (acc[i][2]+bb.z)*pre, (acc[i][3]+bb.w)*pre };
        size_t base = (size_t)(row0+ty*4+i)*H_ + col0 + tx*4;
        __half hv[4], lv[4];
#pragma unroll
        for (int j = 0; j < 4; j++) {
            hv[j] = __float2half(v[j]);
            lv[j] = __float2half(v[j] - __half2float(hv[j]));
        }
        *(uint2*)(ohi + base) = *(uint2*)hv;
        if (wlo) *(uint2*)(g_qlo + base) = *(uint2*)lv;
    }
}

// ---------------------------------------------------------------------------
// Kernel B: FA2-style mma.sync attention (Q,P split fp16x2; K,V plain fp16)
//           + cp.async double-buffered pipeline + LayerNorm + ReLU.
// smem: Qhi | Qlo | K | V | maskbits | gamma | beta   (pitch 528B rows)
// ---------------------------------------------------------------------------
#define PITCH 528
#define SQHI  0
#define SQLO  67584
#define SK    135168
#define SV    168960
#define SMASK 202752
#define SGAM  202880
#define SBET  203904
#define SMEM_ATTN 204928

__global__ __launch_bounds__(256, 1)
void attn_mma_kernel(const int* __restrict__ masks,
                     const float* __restrict__ gamma,
                     const float* __restrict__ beta,
                     float* __restrict__ out)
{
    extern __shared__ char smc[];
    const uint32_t sb = smem_u32(smc);
    const int tid = threadIdx.x, w = tid >> 5, l = tid & 31;
    const int b = blockIdx.y, q0 = blockIdx.x * QT;

    const size_t kb0 = (size_t)(b*N_) * H_;

    // ---- prologue: start K0 and V0 cp.async immediately ----
#pragma unroll
    for (int p = 0; p < 8; p++) {
        int idx = tid + p*256; int r = idx >> 5, c = idx & 31;
        cpa16(sb + SK + (uint32_t)r*PITCH + (uint32_t)c*16, g_khi + kb0 + (size_t)r*H_ + c*8);
    }
    CPA_COMMIT();
#pragma unroll
    for (int p = 0; p < 8; p++) {
        int idx = tid + p*256; int r = idx >> 5, c = idx & 31;
        cpa16(sb + SV + (uint32_t)r*PITCH + (uint32_t)c*16, g_vhi + kb0 + (size_t)r*H_ + c*8);
    }
    CPA_COMMIT();

    // ---- stage Q hi/lo, mask bits, gamma/beta (overlaps with cp.async) ----
    {
        const size_t qb = (size_t)(b*N_ + q0) * H_;
        for (int idx = tid; idx < QT*32; idx += 256) {
            int r = idx >> 5, c = idx & 31;
            uint32_t so = (uint32_t)r*PITCH + (uint32_t)c*16;
            *(uint4*)(smc + SQHI + so) = *(const uint4*)(g_qhi + qb + (size_t)r*H_ + c*8);
            *(uint4*)(smc + SQLO + so) = *(const uint4*)(g_qlo + qb + (size_t)r*H_ + c*8);
        }
        if (tid < 32) {
            uint32_t wbits = 0;
            for (int j = 0; j < 32; j++) wbits |= (masks[b*N_ + tid*32 + j] ? 1u : 0u) << j;
            ((uint32_t*)(smc + SMASK))[tid] = wbits;
        }
        for (int idx = tid; idx < H_; idx += 256) {
            ((float*)(smc + SGAM))[idx] = gamma[idx];
            ((float*)(smc + SBET))[idx] = beta[idx];
        }
    }

    const int r0 = 16*w + (l >> 2), r1 = r0 + 8;
    const bool mq0 = masks[b*N_ + q0 + r0] != 0, mq1 = masks[b*N_ + q0 + r1] != 0;

    float O[32][4];
#pragma unroll
    for (int t = 0; t < 32; t++)
#pragma unroll
        for (int j = 0; j < 4; j++) O[t][j] = 0.0f;
    float ls0 = 0.0f, ls1 = 0.0f;

    const int c0 = 2*(l & 3);
    const uint32_t aoff = (uint32_t)(16*w + (l & 15))*PITCH + (uint32_t)(l >> 4)*16; // Q
    const uint32_t krow = (uint32_t)((l & 7) + ((l >> 4) << 3));
    const uint32_t kcol = (uint32_t)(((l >> 3) & 1))*16;
    const uint32_t vrow = (uint32_t)((l & 7) + (((l >> 3) & 1) << 3));
    const uint32_t vcol = (uint32_t)(l >> 4)*16;

    __syncthreads();

    for (int it = 0; it < 16; it++) {
        CPA_WAIT1();            // K_it arrived (V_it may still be in flight)
        __syncthreads();

        // ---- S = Q·K^T (16x64 per warp): Qhi·K + Qlo·K ----
        float S[8][4];
#pragma unroll
        for (int t = 0; t < 8; t++)
#pragma unroll
            for (int j = 0; j < 4; j++) S[t][j] = 0.0f;

#pragma unroll 4
        for (int kc = 0; kc < 16; kc++) {
            uint32_t Ah[4], Al[4];
            uint32_t ao = aoff + (uint32_t)kc*32;
            ldsm4(Ah, sb + SQHI + ao);
            ldsm4(Al, sb + SQLO + ao);
#pragma unroll
            for (int np = 0; np < 4; np++) {
                uint32_t Bh[4];
                uint32_t ko = (krow + np*16)*PITCH + (uint32_t)kc*32 + kcol;
                ldsm4(Bh, sb + SK + ko);
                mma16816(S[2*np],   Ah, Bh);    mma16816(S[2*np],   Al, Bh);
                mma16816(S[2*np+1], Ah, Bh+2);  mma16816(S[2*np+1], Al, Bh+2);
            }
        }

        // ---- softmax (reference-exact rounding semantics) -> P fragments ----
        const uint32_t w0 = ((uint32_t*)(smc + SMASK))[it*2];
        const uint32_t w1 = ((uint32_t*)(smc + SMASK))[it*2 + 1];
        uint32_t Phi[4][4], Plo[4][4];
#pragma unroll
        for (int j = 0; j < 8; j++) {
            int kidx = j*8 + c0;
            uint32_t mw = (j < 4) ? w0 : w1;
            int sh = kidx & 31;
            bool kb0m = (mw >> sh) & 1, kb1m = (mw >> (sh+1)) & 1;
            float p0 = softp(S[j][0], mq0, kb0m);
            float p1 = softp(S[j][1], mq0, kb1m);
            float p2 = softp(S[j][2], mq1, kb0m);
            float p3 = softp(S[j][3], mq1, kb1m);
            ls0 += p0 + p1; ls1 += p2 + p3;
            __half h0 = __float2half(p0), h1 = __float2half(p1);
            __half h2 = __float2half(p2), h3 = __float2half(p3);
            float l0 = p0 - __half2float(h0), l1 = p1 - __half2float(h1);
            float l2 = p2 - __half2float(h2), l3 = p3 - __half2float(h3);
            int kc = j >> 1, hi = (j & 1) ? 2 : 0;
            Phi[kc][hi+0] = ((uint32_t)__half_as_ushort(h0)) | ((uint32_t)__half_as_ushort(h1) << 16);
            Phi[kc][hi+1] = ((uint32_t)__half_as_ushort(h2)) | ((uint32_t)__half_as_ushort(h3) << 16);
            Plo[kc][hi+0] = packh2(l0, l1);
            Plo[kc][hi+1] = packh2(l2, l3);
        }
        __syncthreads();   // all warps done reading K_it

        // ---- prefetch K_{it+1} (overlaps with PV below) ----
        if (it < 15) {
            const size_t kbn = (size_t)(b*N_ + (it+1)*64) * H_;
#pragma unroll
            for (int p = 0; p < 8; p++) {
                int idx = tid + p*256; int r = idx >> 5, c = idx & 31;
                cpa16(sb + SK + (uint32_t)r*PITCH + (uint32_t)c*16, g_khi + kbn + (size_t)r*H_ + c*8);
            }
        }
        CPA_COMMIT();

        CPA_WAIT1();            // V_it arrived (K_{it+1} may still be in flight)
        __syncthreads();

        // ---- O += P·V (16x256 per warp): Phi·V + Plo·V ----
#pragma unroll
        for (int kc = 0; kc < 4; kc++) {
#pragma unroll
            for (int np = 0; np < 16; np++) {
                uint32_t Bh[4];
                uint32_t vo = (vrow + kc*16)*PITCH + (uint32_t)np*32 + vcol;
                ldsm4t(Bh, sb + SV + vo);
                mma16816(O[2*np],   Phi[kc], Bh);   mma16816(O[2*np],   Plo[kc], Bh);
                mma16816(O[2*np+1], Phi[kc], Bh+2); mma16816(O[2*np+1], Plo[kc], Bh+2);
            }
        }
        __syncthreads();   // all warps done reading V_it

        // ---- prefetch V_{it+1} (overlaps with next S phase) ----
        if (it < 15) {
            const size_t vbn = (size_t)(b*N_ + (it+1)*64) * H_;
#pragma unroll
            for (int p = 0; p < 8; p++) {
                int idx = tid + p*256; int r = idx >> 5, c = idx & 31;
                cpa16(sb + SV + (uint32_t)r*PITCH + (uint32_t)c*16, g_vhi + vbn + (size_t)r*H_ + c*8);
            }
        }
        CPA_COMMIT();
    }

    // ---- epilogue: /l, LayerNorm (x16-invariant), ReLU, store ----
    ls0 += __shfl_xor_sync(0xffffffffu, ls0, 1); ls0 += __shfl_xor_sync(0xffffffffu, ls0, 2);
    ls1 += __shfl_xor_sync(0xffffffffu, ls1, 1); ls1 += __shfl_xor_sync(0xffffffffu, ls1, 2);
    const float inv0 = 1.0f / ls0, inv1 = 1.0f / ls1;

    float s0 = 0.0f, q0s = 0.0f, s1 = 0.0f, q1s = 0.0f;
#pragma unroll
    for (int t = 0; t < 32; t++) {
        float v0 = O[t][0]*inv0, v1 = O[t][1]*inv0;
        float v2 = O[t][2]*inv1, v3 = O[t][3]*inv1;
        s0 += v0 + v1; q0s = fmaf(v0,v0,fmaf(v1,v1,q0s));
        s1 += v2 + v3; q1s = fmaf(v2,v2,fmaf(v3,v3,q1s));
    }
    s0 += __shfl_xor_sync(0xffffffffu, s0, 1); s0 += __shfl_xor_sync(0xffffffffu, s0, 2);
    q0s += __shfl_xor_sync(0xffffffffu, q0s, 1); q0s += __shfl_xor_sync(0xffffffffu, q0s, 2);
    s1 += __shfl_xor_sync(0xffffffffu, s1, 1); s1 += __shfl_xor_sync(0xffffffffu, s1, 2);
    q1s += __shfl_xor_sync(0xffffffffu, q1s, 1); q1s += __shfl_xor_sync(0xffffffffu, q1s, 2);

    // (16o - 16mu)*rsqrt(256var + 256eps) = (o - mu)*rsqrt(var + eps)
    const float mu0 = s0 * (1.0f/H_), mu1 = s1 * (1.0f/H_);
    const float rstd0 = rsqrtf(fmaxf(q0s*(1.0f/H_) - mu0*mu0, 0.0f) + 1e-5f*256.0f);
    const float rstd1 = rsqrtf(fmaxf(q1s*(1.0f/H_) - mu1*mu1, 0.0f) + 1e-5f*256.0f);

    const float* gsm = (const float*)(smc + SGAM);
    const float* bsm = (const float*)(smc + SBET);
    const size_t ob0 = (size_t)(b*N_ + q0 + r0) * H_;
    const size_t ob1 = (size_t)(b*N_ + q0 + r1) * H_;
#pragma unroll
    for (int t = 0; t < 32; t++) {
        int col = t*8 + c0;
        float2 y0, y1;
        y0.x = fmaxf((O[t][0]*inv0 - mu0)*rstd0*gsm[col]   + bsm[col],   0.0f);
        y0.y = fmaxf((O[t][1]*inv0 - mu0)*rstd0*gsm[col+1] + bsm[col+1], 0.0f);
        y1.x = fmaxf((O[t][2]*inv1 - mu1)*rstd1*gsm[col]   + bsm[col],   0.0f);
        y1.y = fmaxf((O[t][3]*inv1 - mu1)*rstd1*gsm[col+1] + bsm[col+1], 0.0f);
        *(float2*)(out + ob0 + col) = y0;
        *(float2*)(out + ob1 + col) = y1;
    }
}

// ---------------------------------------------------------------------------
extern "C" void kernel_launch(void* const* d_in, const int* in_sizes, int n_in,
                              void* d_out, int out_size)
{
    const float* feats = (const float*)d_in[0];
    const int*   masks = (const int*)d_in[1];
    const float* Wq = (const float*)d_in[2];
    const float* bq = (const float*)d_in[3];
    const float* Wk = (const float*)d_in[4];
    const float* bk = (const float*)d_in[5];
    const float* Wv = (const float*)d_in[6];
    const float* bv = (const float*)d_in[7];
    const float* gamma = (const float*)d_in[8];
    const float* beta  = (const float*)d_in[9];
    float* out = (float*)d_out;

    dim3 gA((B_*N_)/64, H_/64, 3);
    qkv_kernel<<<gA, 256>>>(feats, Wq, bq, Wk, bk, Wv, bv);

    cudaFuncSetAttribute(attn_mma_kernel,
                         cudaFuncAttributeMaxDynamicSharedMemorySize,
                         SMEM_ATTN);
    dim3 gB(N_/QT, B_);
    attn_mma_kernel<<<gB, 256, SMEM_ATTN>>>(masks, gamma, beta, out);
}

// round 15
// speedup vs baseline: 3.1749x; 1.3465x over previous
#include <cuda_runtime.h>
#include <cuda_fp16.h>
#include <cstdint>
#include <cstddef>

#define B_ 32
#define N_ 1024
#define H_ 256
#define QT 128

// Q,K,V all scaled x16 (keeps fp16 planes out of subnormal range).
// S_mma = 256*(q.k); softmax applies 1/4096 then shift. V x16 cancels in LayerNorm.
#define SSCALE 2.44140625e-4f   // 1/4096

__device__ __half g_qhi[B_*N_*H_], g_qlo[B_*N_*H_];
__device__ __half g_khi[B_*N_*H_];
__device__ __half g_vhi[B_*N_*H_];
__device__ __half g_fhi[B_*N_*H_], g_flo[B_*N_*H_];      // feats split
__device__ __half g_wthi[3*H_*H_], g_wtlo[3*H_*H_];      // 16*W^T split (n-major)

// ---------------- helpers ----------------
__device__ __forceinline__ uint32_t smem_u32(const void* p) {
    uint32_t a;
    asm("{ .reg .u64 t; cvta.to.shared.u64 t, %1; cvt.u32.u64 %0, t; }" : "=r"(a) : "l"(p));
    return a;
}
__device__ __forceinline__ void ldsm4(uint32_t* r, uint32_t a) {
    asm volatile("ldmatrix.sync.aligned.m8n8.x4.shared.b16 {%0,%1,%2,%3}, [%4];"
        : "=r"(r[0]), "=r"(r[1]), "=r"(r[2]), "=r"(r[3]) : "r"(a));
}
__device__ __forceinline__ void ldsm4t(uint32_t* r, uint32_t a) {
    asm volatile("ldmatrix.sync.aligned.m8n8.x4.trans.shared.b16 {%0,%1,%2,%3}, [%4];"
        : "=r"(r[0]), "=r"(r[1]), "=r"(r[2]), "=r"(r[3]) : "r"(a));
}
__device__ __forceinline__ void mma16816(float* d, const uint32_t* a, const uint32_t* b) {
    asm volatile("mma.sync.aligned.m16n8k16.row.col.f32.f16.f16.f32 "
        "{%0,%1,%2,%3}, {%4,%5,%6,%7}, {%8,%9}, {%0,%1,%2,%3};"
        : "+f"(d[0]), "+f"(d[1]), "+f"(d[2]), "+f"(d[3])
        : "r"(a[0]), "r"(a[1]), "r"(a[2]), "r"(a[3]), "r"(b[0]), "r"(b[1]));
}
__device__ __forceinline__ uint32_t packh2(float a, float b) {
    __half2 t = __floats2half2_rn(a, b);
    return *(uint32_t*)&t;
}
__device__ __forceinline__ void cpa16(uint32_t s, const void* g) {
    asm volatile("cp.async.cg.shared.global [%0], [%1], 16;" :: "r"(s), "l"(g));
}
#define CPA_COMMIT() asm volatile("cp.async.commit_group;" ::: "memory")
#define CPA_WAIT1()  asm volatile("cp.async.wait_group 1;" ::: "memory")

// Softmax numerator replicating the REFERENCE's fp32 rounding semantics.
__device__ __forceinline__ float softp(float smma, bool rowvalid, bool keyvalid) {
    float s = __fmul_rn(smma, SSCALE);
    if (rowvalid) {
        return keyvalid ? __expf(__fadd_rn(s, -5.0f)) : 0.0f;
    } else {
        float t  = __fadd_rn(s, -100000.0f);
        float sq = __fadd_rn(t,  100000.0f);
        return __expf(__fadd_rn(sq, -6.0f));
    }
}

// ---------------------------------------------------------------------------
// Prep 1: split feats -> fp16 hi/lo (unscaled; x16 rides on W).
// ---------------------------------------------------------------------------
__global__ __launch_bounds__(256, 4)
void split_feats_kernel(const float* __restrict__ feats)
{
    int i = blockIdx.x * 256 + threadIdx.x;      // < 2097152 float4s
    float4 v = ((const float4*)feats)[i];
    __half h[4], lo[4];
    float f[4] = {v.x, v.y, v.z, v.w};
#pragma unroll
    for (int j = 0; j < 4; j++) {
        h[j]  = __float2half(f[j]);
        lo[j] = __float2half(f[j] - __half2float(h[j]));
    }
    *(uint2*)(g_fhi + (size_t)i*4) = *(uint2*)h;
    *(uint2*)(g_flo + (size_t)i*4) = *(uint2*)lo;
}

// ---------------------------------------------------------------------------
// Prep 2: split 16*W^T -> fp16 hi/lo, n-major (rows=n, cols=k).
// ---------------------------------------------------------------------------
__global__ __launch_bounds__(256, 4)
void split_w_kernel(const float* __restrict__ Wq,
                    const float* __restrict__ Wk,
                    const float* __restrict__ Wv)
{
    int z = blockIdx.y, n = blockIdx.x, k = threadIdx.x;
    const float* W = (z == 0) ? Wq : (z == 1) ? Wk : Wv;
    float v = 16.0f * W[k * H_ + n];
    __half h = __float2half(v);
    g_wthi[z*H_*H_ + n*H_ + k] = h;
    g_wtlo[z*H_*H_ + n*H_ + k] = __float2half(v - __half2float(h));
}

// ---------------------------------------------------------------------------
// Kernel A: QKV projection via mma.sync fp16x3.
// C = feats @ (16 W) + 16 b -> fp16 hi (+lo for Q).
// CTA: 128 rows x 256 cols; 8 warps = 4(M) x 2(N); K chunked x32,
// B double-buffered via cp.async; A resident in smem.
// ---------------------------------------------------------------------------
#define APITCH 528
#define BPITCH 80
#define SA_HI 0
#define SA_LO 67584
#define SBB   135168          // 2 buffers x (hi 20480 | lo 20480), stride 40960
#define SMEM_QKV 217088

__global__ __launch_bounds__(256, 1)
void qkv_mma_kernel(const float* __restrict__ bq,
                    const float* __restrict__ bk,
                    const float* __restrict__ bv)
{
    extern __shared__ char smc[];
    const uint32_t sb = smem_u32(smc);
    const int tid = threadIdx.x, w = tid >> 5, l = tid & 31;
    const int z = blockIdx.z;
    const int row0 = blockIdx.x * 128;

    const __half* wthi = g_wthi + z*H_*H_;
    const __half* wtlo = g_wtlo + z*H_*H_;
    const float* bias = (z == 0) ? bq : (z == 1) ? bk : bv;
    __half* ohi = (z == 0) ? g_qhi : (z == 1) ? g_khi : g_vhi;

    // prologue: A hi/lo + B chunk0 (group0), B chunk1 (group1)
#pragma unroll
    for (int p = 0; p < 16; p++) {
        int idx = tid + p*256; int r = idx >> 5, c = idx & 31;
        cpa16(sb + SA_HI + (uint32_t)r*APITCH + (uint32_t)c*16, g_fhi + (size_t)(row0+r)*H_ + c*8);
    }
#pragma unroll
    for (int p = 0; p < 16; p++) {
        int idx = tid + p*256; int r = idx >> 5, c = idx & 31;
        cpa16(sb + SA_LO + (uint32_t)r*APITCH + (uint32_t)c*16, g_flo + (size_t)(row0+r)*H_ + c*8);
    }
#pragma unroll
    for (int p = 0; p < 4; p++) {
        int idx = tid + p*256; int n = idx >> 2, c = idx & 3;
        cpa16(sb + SBB + (uint32_t)n*BPITCH + (uint32_t)c*16, wthi + n*H_ + c*8);
        cpa16(sb + SBB + 20480 + (uint32_t)n*BPITCH + (uint32_t)c*16, wtlo + n*H_ + c*8);
    }
    CPA_COMMIT();
#pragma unroll
    for (int p = 0; p < 4; p++) {
        int idx = tid + p*256; int n = idx >> 2, c = idx & 3;
        cpa16(sb + SBB + 40960 + (uint32_t)n*BPITCH + (uint32_t)c*16, wthi + n*H_ + 32 + c*8);
        cpa16(sb + SBB + 40960 + 20480 + (uint32_t)n*BPITCH + (uint32_t)c*16, wtlo + n*H_ + 32 + c*8);
    }
    CPA_COMMIT();

    const int wm = w >> 1, wn = w & 1;
    float C[2][16][4];
#pragma unroll
    for (int mt = 0; mt < 2; mt++)
#pragma unroll
        for (int j = 0; j < 16; j++)
#pragma unroll
            for (int q = 0; q < 4; q++) C[mt][j][q] = 0.0f;

    const uint32_t krow = (uint32_t)((l & 7) + ((l >> 4) << 3));
    const uint32_t kcol = (uint32_t)(((l >> 3) & 1)) * 16;
    const uint32_t abase0 = (uint32_t)(32*wm + (l & 15))*APITCH + (uint32_t)(l >> 4)*16;
    const uint32_t abase1 = abase0 + 16*APITCH;

    for (int ch = 0; ch < 8; ch++) {
        CPA_WAIT1();
        __syncthreads();
        const uint32_t bbuf = sb + SBB + (uint32_t)(ch & 1)*40960;
#pragma unroll
        for (int kc2 = 0; kc2 < 2; kc2++) {
            const int kk = ch*2 + kc2;
            uint32_t Ah0[4], Al0[4], Ah1[4], Al1[4];
            ldsm4(Ah0, sb + SA_HI + abase0 + (uint32_t)kk*32);
            ldsm4(Al0, sb + SA_LO + abase0 + (uint32_t)kk*32);
            ldsm4(Ah1, sb + SA_HI + abase1 + (uint32_t)kk*32);
            ldsm4(Al1, sb + SA_LO + abase1 + (uint32_t)kk*32);
#pragma unroll
            for (int np = 0; np < 8; np++) {
                uint32_t Bh[4], Bl[4];
                uint32_t bo = (krow + (uint32_t)(wn*128 + np*16))*BPITCH + (uint32_t)kc2*32 + kcol;
                ldsm4(Bh, bbuf + bo);
                ldsm4(Bl, bbuf + 20480 + bo);
                mma16816(C[0][2*np],   Ah0, Bh);   mma16816(C[0][2*np],   Ah0, Bl);   mma16816(C[0][2*np],   Al0, Bh);
                mma16816(C[0][2*np+1], Ah0, Bh+2); mma16816(C[0][2*np+1], Ah0, Bl+2); mma16816(C[0][2*np+1], Al0, Bh+2);
                mma16816(C[1][2*np],   Ah1, Bh);   mma16816(C[1][2*np],   Ah1, Bl);   mma16816(C[1][2*np],   Al1, Bh);
                mma16816(C[1][2*np+1], Ah1, Bh+2); mma16816(C[1][2*np+1], Ah1, Bl+2); mma16816(C[1][2*np+1], Al1, Bh+2);
            }
        }
        __syncthreads();
        if (ch + 2 < 8) {
            const int k0 = (ch + 2)*32;
            const uint32_t dst = sb + SBB + (uint32_t)(ch & 1)*40960;
#pragma unroll
            for (int p = 0; p < 4; p++) {
                int idx = tid + p*256; int n = idx >> 2, c = idx & 3;
                cpa16(dst + (uint32_t)n*BPITCH + (uint32_t)c*16, wthi + n*H_ + k0 + c*8);
                cpa16(dst + 20480 + (uint32_t)n*BPITCH + (uint32_t)c*16, wtlo + n*H_ + k0 + c*8);
            }
        }
        CPA_COMMIT();
    }

    // epilogue: + 16*bias, split fp16 (Q also lo plane)
    const int c0 = 2*(l & 3);
#pragma unroll
    for (int mt = 0; mt < 2; mt++) {
        const int r0 = row0 + 32*wm + 16*mt + (l >> 2);
#pragma unroll
        for (int jn = 0; jn < 16; jn++) {
            const int col = wn*128 + jn*8 + c0;
            const float b0 = 16.0f*bias[col], b1 = 16.0f*bias[col+1];
            float v0 = C[mt][jn][0] + b0, v1 = C[mt][jn][1] + b1;
            float v2 = C[mt][jn][2] + b0, v3 = C[mt][jn][3] + b1;
            __half h0 = __float2half(v0), h1 = __float2half(v1);
            __half h2 = __float2half(v2), h3 = __float2half(v3);
            *(uint32_t*)(ohi + (size_t)r0*H_ + col) =
                ((uint32_t)__half_as_ushort(h0)) | ((uint32_t)__half_as_ushort(h1) << 16);
            *(uint32_t*)(ohi + (size_t)(r0+8)*H_ + col) =
                ((uint32_t)__half_as_ushort(h2)) | ((uint32_t)__half_as_ushort(h3) << 16);
            if (z == 0) {
                *(uint32_t*)(g_qlo + (size_t)r0*H_ + col) =
                    packh2(v0 - __half2float(h0), v1 - __half2float(h1));
                *(uint32_t*)(g_qlo + (size_t)(r0+8)*H_ + col) =
                    packh2(v2 - __half2float(h2), v3 - __half2float(h3));
            }
        }
    }
}

// ---------------------------------------------------------------------------
// Kernel B: FA2-style mma.sync attention (Q,P split fp16x2; K,V plain fp16)
//           + cp.async double-buffered pipeline + LayerNorm + ReLU.
// ---------------------------------------------------------------------------
#define PITCH 528
#define SQHI  0
#define SQLO  67584
#define SK    135168
#define SV    168960
#define SMASK 202752
#define SGAM  202880
#define SBET  203904
#define SMEM_ATTN 204928

__global__ __launch_bounds__(256, 1)
void attn_mma_kernel(const int* __restrict__ masks,
                     const float* __restrict__ gamma,
                     const float* __restrict__ beta,
                     float* __restrict__ out)
{
    extern __shared__ char smc[];
    const uint32_t sb = smem_u32(smc);
    const int tid = threadIdx.x, w = tid >> 5, l = tid & 31;
    const int b = blockIdx.y, q0 = blockIdx.x * QT;

    const size_t kb0 = (size_t)(b*N_) * H_;

#pragma unroll
    for (int p = 0; p < 8; p++) {
        int idx = tid + p*256; int r = idx >> 5, c = idx & 31;
        cpa16(sb + SK + (uint32_t)r*PITCH + (uint32_t)c*16, g_khi + kb0 + (size_t)r*H_ + c*8);
    }
    CPA_COMMIT();
#pragma unroll
    for (int p = 0; p < 8; p++) {
        int idx = tid + p*256; int r = idx >> 5, c = idx & 31;
        cpa16(sb + SV + (uint32_t)r*PITCH + (uint32_t)c*16, g_vhi + kb0 + (size_t)r*H_ + c*8);
    }
    CPA_COMMIT();

    {
        const size_t qb = (size_t)(b*N_ + q0) * H_;
        for (int idx = tid; idx < QT*32; idx += 256) {
            int r = idx >> 5, c = idx & 31;
            uint32_t so = (uint32_t)r*PITCH + (uint32_t)c*16;
            *(uint4*)(smc + SQHI + so) = *(const uint4*)(g_qhi + qb + (size_t)r*H_ + c*8);
            *(uint4*)(smc + SQLO + so) = *(const uint4*)(g_qlo + qb + (size_t)r*H_ + c*8);
        }
        if (tid < 32) {
            uint32_t wbits = 0;
            for (int j = 0; j < 32; j++) wbits |= (masks[b*N_ + tid*32 + j] ? 1u : 0u) << j;
            ((uint32_t*)(smc + SMASK))[tid] = wbits;
        }
        for (int idx = tid; idx < H_; idx += 256) {
            ((float*)(smc + SGAM))[idx] = gamma[idx];
            ((float*)(smc + SBET))[idx] = beta[idx];
        }
    }

    const int r0 = 16*w + (l >> 2), r1 = r0 + 8;
    const bool mq0 = masks[b*N_ + q0 + r0] != 0, mq1 = masks[b*N_ + q0 + r1] != 0;

    float O[32][4];
#pragma unroll
    for (int t = 0; t < 32; t++)
#pragma unroll
        for (int j = 0; j < 4; j++) O[t][j] = 0.0f;
    float ls0 = 0.0f, ls1 = 0.0f;

    const int c0 = 2*(l & 3);
    const uint32_t aoff = (uint32_t)(16*w + (l & 15))*PITCH + (uint32_t)(l >> 4)*16;
    const uint32_t krow = (uint32_t)((l & 7) + ((l >> 4) << 3));
    const uint32_t kcol = (uint32_t)(((l >> 3) & 1))*16;
    const uint32_t vrow = (uint32_t)((l & 7) + (((l >> 3) & 1) << 3));
    const uint32_t vcol = (uint32_t)(l >> 4)*16;

    __syncthreads();

    for (int it = 0; it < 16; it++) {
        CPA_WAIT1();
        __syncthreads();

        float S[8][4];
#pragma unroll
        for (int t = 0; t < 8; t++)
#pragma unroll
            for (int j = 0; j < 4; j++) S[t][j] = 0.0f;

#pragma unroll 4
        for (int kc = 0; kc < 16; kc++) {
            uint32_t Ah[4], Al[4];
            uint32_t ao = aoff + (uint32_t)kc*32;
            ldsm4(Ah, sb + SQHI + ao);
            ldsm4(Al, sb + SQLO + ao);
#pragma unroll
            for (int np = 0; np < 4; np++) {
                uint32_t Bh[4];
                uint32_t ko = (krow + np*16)*PITCH + (uint32_t)kc*32 + kcol;
                ldsm4(Bh, sb + SK + ko);
                mma16816(S[2*np],   Ah, Bh);    mma16816(S[2*np],   Al, Bh);
                mma16816(S[2*np+1], Ah, Bh+2);  mma16816(S[2*np+1], Al, Bh+2);
            }
        }

        const uint32_t w0 = ((uint32_t*)(smc + SMASK))[it*2];
        const uint32_t w1 = ((uint32_t*)(smc + SMASK))[it*2 + 1];
        uint32_t Phi[4][4], Plo[4][4];
#pragma unroll
        for (int j = 0; j < 8; j++) {
            int kidx = j*8 + c0;
            uint32_t mw = (j < 4) ? w0 : w1;
            int sh = kidx & 31;
            bool kb0m = (mw >> sh) & 1, kb1m = (mw >> (sh+1)) & 1;
            float p0 = softp(S[j][0], mq0, kb0m);
            float p1 = softp(S[j][1], mq0, kb1m);
            float p2 = softp(S[j][2], mq1, kb0m);
            float p3 = softp(S[j][3], mq1, kb1m);
            ls0 += p0 + p1; ls1 += p2 + p3;
            __half h0 = __float2half(p0), h1 = __float2half(p1);
            __half h2 = __float2half(p2), h3 = __float2half(p3);
            float l0 = p0 - __half2float(h0), l1 = p1 - __half2float(h1);
            float l2 = p2 - __half2float(h2), l3 = p3 - __half2float(h3);
            int kc = j >> 1, hi = (j & 1) ? 2 : 0;
            Phi[kc][hi+0] = ((uint32_t)__half_as_ushort(h0)) | ((uint32_t)__half_as_ushort(h1) << 16);
            Phi[kc][hi+1] = ((uint32_t)__half_as_ushort(h2)) | ((uint32_t)__half_as_ushort(h3) << 16);
            Plo[kc][hi+0] = packh2(l0, l1);
            Plo[kc][hi+1] = packh2(l2, l3);
        }
        __syncthreads();

        if (it < 15) {
            const size_t kbn = (size_t)(b*N_ + (it+1)*64) * H_;
#pragma unroll
            for (int p = 0; p < 8; p++) {
                int idx = tid + p*256; int r = idx >> 5, c = idx & 31;
                cpa16(sb + SK + (uint32_t)r*PITCH + (uint32_t)c*16, g_khi + kbn + (size_t)r*H_ + c*8);
            }
        }
        CPA_COMMIT();

        CPA_WAIT1();
        __syncthreads();

#pragma unroll
        for (int kc = 0; kc < 4; kc++) {
#pragma unroll
            for (int np = 0; np < 16; np++) {
                uint32_t Bh[4];
                uint32_t vo = (vrow + kc*16)*PITCH + (uint32_t)np*32 + vcol;
                ldsm4t(Bh, sb + SV + vo);
                mma16816(O[2*np],   Phi[kc], Bh);   mma16816(O[2*np],   Plo[kc], Bh);
                mma16816(O[2*np+1], Phi[kc], Bh+2); mma16816(O[2*np+1], Plo[kc], Bh+2);
            }
        }
        __syncthreads();

        if (it < 15) {
            const size_t vbn = (size_t)(b*N_ + (it+1)*64) * H_;
#pragma unroll
            for (int p = 0; p < 8; p++) {
                int idx = tid + p*256; int r = idx >> 5, c = idx & 31;
                cpa16(sb + SV + (uint32_t)r*PITCH + (uint32_t)c*16, g_vhi + vbn + (size_t)r*H_ + c*8);
            }
        }
        CPA_COMMIT();
    }

    ls0 += __shfl_xor_sync(0xffffffffu, ls0, 1); ls0 += __shfl_xor_sync(0xffffffffu, ls0, 2);
    ls1 += __shfl_xor_sync(0xffffffffu, ls1, 1); ls1 += __shfl_xor_sync(0xffffffffu, ls1, 2);
    const float inv0 = 1.0f / ls0, inv1 = 1.0f / ls1;

    float s0 = 0.0f, q0s = 0.0f, s1 = 0.0f, q1s = 0.0f;
#pragma unroll
    for (int t = 0; t < 32; t++) {
        float v0 = O[t][0]*inv0, v1 = O[t][1]*inv0;
        float v2 = O[t][2]*inv1, v3 = O[t][3]*inv1;
        s0 += v0 + v1; q0s = fmaf(v0,v0,fmaf(v1,v1,q0s));
        s1 += v2 + v3; q1s = fmaf(v2,v2,fmaf(v3,v3,q1s));
    }
    s0 += __shfl_xor_sync(0xffffffffu, s0, 1); s0 += __shfl_xor_sync(0xffffffffu, s0, 2);
    q0s += __shfl_xor_sync(0xffffffffu, q0s, 1); q0s += __shfl_xor_sync(0xffffffffu, q0s, 2);
    s1 += __shfl_xor_sync(0xffffffffu, s1, 1); s1 += __shfl_xor_sync(0xffffffffu, s1, 2);
    q1s += __shfl_xor_sync(0xffffffffu, q1s, 1); q1s += __shfl_xor_sync(0xffffffffu, q1s, 2);

    // (16o - 16mu)*rsqrt(256var + 256eps) = (o - mu)*rsqrt(var + eps)
    const float mu0 = s0 * (1.0f/H_), mu1 = s1 * (1.0f/H_);
    const float rstd0 = rsqrtf(fmaxf(q0s*(1.0f/H_) - mu0*mu0, 0.0f) + 1e-5f*256.0f);
    const float rstd1 = rsqrtf(fmaxf(q1s*(1.0f/H_) - mu1*mu1, 0.0f) + 1e-5f*256.0f);

    const float* gsm = (const float*)(smc + SGAM);
    const float* bsm = (const float*)(smc + SBET);
    const size_t ob0 = (size_t)(b*N_ + q0 + r0) * H_;
    const size_t ob1 = (size_t)(b*N_ + q0 + r1) * H_;
#pragma unroll
    for (int t = 0; t < 32; t++) {
        int col = t*8 + c0;
        float2 y0, y1;
        y0.x = fmaxf((O[t][0]*inv0 - mu0)*rstd0*gsm[col]   + bsm[col],   0.0f);
        y0.y = fmaxf((O[t][1]*inv0 - mu0)*rstd0*gsm[col+1] + bsm[col+1], 0.0f);
        y1.x = fmaxf((O[t][2]*inv1 - mu1)*rstd1*gsm[col]   + bsm[col],   0.0f);
        y1.y = fmaxf((O[t][3]*inv1 - mu1)*rstd1*gsm[col+1] + bsm[col+1], 0.0f);
        *(float2*)(out + ob0 + col) = y0;
        *(float2*)(out + ob1 + col) = y1;
    }
}

// ---------------------------------------------------------------------------
extern "C" void kernel_launch(void* const* d_in, const int* in_sizes, int n_in,
                              void* d_out, int out_size)
{
    const float* feats = (const float*)d_in[0];
    const int*   masks = (const int*)d_in[1];
    const float* Wq = (const float*)d_in[2];
    const float* bq = (const float*)d_in[3];
    const float* Wk = (const float*)d_in[4];
    const float* bk = (const float*)d_in[5];
    const float* Wv = (const float*)d_in[6];
    const float* bv = (const float*)d_in[7];
    const float* gamma = (const float*)d_in[8];
    const float* beta  = (const float*)d_in[9];
    float* out = (float*)d_out;

    split_feats_kernel<<<(B_*N_*H_)/(256*4), 256>>>(feats);
    split_w_kernel<<<dim3(H_, 3), 256>>>(Wq, Wk, Wv);

    cudaFuncSetAttribute(qkv_mma_kernel,
                         cudaFuncAttributeMaxDynamicSharedMemorySize,
                         SMEM_QKV);
    qkv_mma_kernel<<<dim3((B_*N_)/128, 1, 3), 256, SMEM_QKV>>>(bq, bk, bv);

    cudaFuncSetAttribute(attn_mma_kernel,
                         cudaFuncAttributeMaxDynamicSharedMemorySize,
                         SMEM_ATTN);
    dim3 gB(N_/QT, B_);
    attn_mma_kernel<<<gB, 256, SMEM_ATTN>>>(masks, gamma, beta, out);
}

// round 16
// speedup vs baseline: 3.4626x; 1.0906x over previous
#include <cuda_runtime.h>
#include <cuda_fp16.h>
#include <cstdint>
#include <cstddef>

#define B_ 32
#define N_ 1024
#define H_ 256
#define QT 128

// Q,K,V all scaled x16 (keeps fp16 planes out of subnormal range).
// S_mma = 256*(q.k); softmax applies 1/4096 then shift. V x16 cancels in LayerNorm.
#define SSCALE 2.44140625e-4f   // 1/4096

__device__ __half g_qhi[B_*N_*H_], g_qlo[B_*N_*H_];
__device__ __half g_khi[B_*N_*H_];
__device__ __half g_vhi[B_*N_*H_];
__device__ __half g_fhi[B_*N_*H_], g_flo[B_*N_*H_];      // feats split
__device__ __half g_wthi[3*H_*H_], g_wtlo[3*H_*H_];      // 16*W^T split (n-major)

// ---------------- helpers ----------------
__device__ __forceinline__ uint32_t smem_u32(const void* p) {
    uint32_t a;
    asm("{ .reg .u64 t; cvta.to.shared.u64 t, %1; cvt.u32.u64 %0, t; }" : "=r"(a) : "l"(p));
    return a;
}
__device__ __forceinline__ void ldsm4(uint32_t* r, uint32_t a) {
    asm volatile("ldmatrix.sync.aligned.m8n8.x4.shared.b16 {%0,%1,%2,%3}, [%4];"
        : "=r"(r[0]), "=r"(r[1]), "=r"(r[2]), "=r"(r[3]) : "r"(a));
}
__device__ __forceinline__ void ldsm4t(uint32_t* r, uint32_t a) {
    asm volatile("ldmatrix.sync.aligned.m8n8.x4.trans.shared.b16 {%0,%1,%2,%3}, [%4];"
        : "=r"(r[0]), "=r"(r[1]), "=r"(r[2]), "=r"(r[3]) : "r"(a));
}
__device__ __forceinline__ void mma16816(float* d, const uint32_t* a, const uint32_t* b) {
    asm volatile("mma.sync.aligned.m16n8k16.row.col.f32.f16.f16.f32 "
        "{%0,%1,%2,%3}, {%4,%5,%6,%7}, {%8,%9}, {%0,%1,%2,%3};"
        : "+f"(d[0]), "+f"(d[1]), "+f"(d[2]), "+f"(d[3])
        : "r"(a[0]), "r"(a[1]), "r"(a[2]), "r"(a[3]), "r"(b[0]), "r"(b[1]));
}
__device__ __forceinline__ uint32_t packh2(float a, float b) {
    __half2 t = __floats2half2_rn(a, b);
    return *(uint32_t*)&t;
}
__device__ __forceinline__ void cpa16(uint32_t s, const void* g) {
    asm volatile("cp.async.cg.shared.global [%0], [%1], 16;" :: "r"(s), "l"(g));
}
#define CPA_COMMIT() asm volatile("cp.async.commit_group;" ::: "memory")
#define CPA_WAIT1()  asm volatile("cp.async.wait_group 1;" ::: "memory")

// Softmax numerator replicating the REFERENCE's fp32 rounding semantics.
__device__ __forceinline__ float softp(float smma, bool rowvalid, bool keyvalid) {
    float s = __fmul_rn(smma, SSCALE);
    if (rowvalid) {
        return keyvalid ? __expf(__fadd_rn(s, -5.0f)) : 0.0f;
    } else {
        float t  = __fadd_rn(s, -100000.0f);
        float sq = __fadd_rn(t,  100000.0f);
        return __expf(__fadd_rn(sq, -6.0f));
    }
}

// ---------------------------------------------------------------------------
// Prep 1: split feats -> fp16 hi/lo (unscaled; x16 rides on W).
// ---------------------------------------------------------------------------
__global__ __launch_bounds__(256, 4)
void split_feats_kernel(const float* __restrict__ feats)
{
    int i = blockIdx.x * 256 + threadIdx.x;      // < 2097152 float4s
    float4 v = ((const float4*)feats)[i];
    __half h[4], lo[4];
    float f[4] = {v.x, v.y, v.z, v.w};
#pragma unroll
    for (int j = 0; j < 4; j++) {
        h[j]  = __float2half(f[j]);
        lo[j] = __float2half(f[j] - __half2float(h[j]));
    }
    *(uint2*)(g_fhi + (size_t)i*4) = *(uint2*)h;
    *(uint2*)(g_flo + (size_t)i*4) = *(uint2*)lo;
}

// ---------------------------------------------------------------------------
// Prep 2: split 16*W^T -> fp16 hi/lo, n-major (rows=n, cols=k).
// ---------------------------------------------------------------------------
__global__ __launch_bounds__(256, 4)
void split_w_kernel(const float* __restrict__ Wq,
                    const float* __restrict__ Wk,
                    const float* __restrict__ Wv)
{
    int z = blockIdx.y, n = blockIdx.x, k = threadIdx.x;
    const float* W = (z == 0) ? Wq : (z == 1) ? Wk : Wv;
    float v = 16.0f * W[k * H_ + n];
    __half h = __float2half(v);
    g_wthi[z*H_*H_ + n*H_ + k] = h;
    g_wtlo[z*H_*H_ + n*H_ + k] = __float2half(v - __half2float(h));
}

// ---------------------------------------------------------------------------
// Kernel A: QKV projection via mma.sync fp16x3.
// ---------------------------------------------------------------------------
#define APITCH 528
#define BPITCH 80
#define SA_HI 0
#define SA_LO 67584
#define SBB   135168          // 2 buffers x (hi 20480 | lo 20480), stride 40960
#define SMEM_QKV 217088

__global__ __launch_bounds__(256, 1)
void qkv_mma_kernel(const float* __restrict__ bq,
                    const float* __restrict__ bk,
                    const float* __restrict__ bv)
{
    extern __shared__ char smc[];
    const uint32_t sb = smem_u32(smc);
    const int tid = threadIdx.x, w = tid >> 5, l = tid & 31;
    const int z = blockIdx.z;
    const int row0 = blockIdx.x * 128;

    const __half* wthi = g_wthi + z*H_*H_;
    const __half* wtlo = g_wtlo + z*H_*H_;
    const float* bias = (z == 0) ? bq : (z == 1) ? bk : bv;
    __half* ohi = (z == 0) ? g_qhi : (z == 1) ? g_khi : g_vhi;

#pragma unroll
    for (int p = 0; p < 16; p++) {
        int idx = tid + p*256; int r = idx >> 5, c = idx & 31;
        cpa16(sb + SA_HI + (uint32_t)r*APITCH + (uint32_t)c*16, g_fhi + (size_t)(row0+r)*H_ + c*8);
    }
#pragma unroll
    for (int p = 0; p < 16; p++) {
        int idx = tid + p*256; int r = idx >> 5, c = idx & 31;
        cpa16(sb + SA_LO + (uint32_t)r*APITCH + (uint32_t)c*16, g_flo + (size_t)(row0+r)*H_ + c*8);
    }
#pragma unroll
    for (int p = 0; p < 4; p++) {
        int idx = tid + p*256; int n = idx >> 2, c = idx & 3;
        cpa16(sb + SBB + (uint32_t)n*BPITCH + (uint32_t)c*16, wthi + n*H_ + c*8);
        cpa16(sb + SBB + 20480 + (uint32_t)n*BPITCH + (uint32_t)c*16, wtlo + n*H_ + c*8);
    }
    CPA_COMMIT();
#pragma unroll
    for (int p = 0; p < 4; p++) {
        int idx = tid + p*256; int n = idx >> 2, c = idx & 3;
        cpa16(sb + SBB + 40960 + (uint32_t)n*BPITCH + (uint32_t)c*16, wthi + n*H_ + 32 + c*8);
        cpa16(sb + SBB + 40960 + 20480 + (uint32_t)n*BPITCH + (uint32_t)c*16, wtlo + n*H_ + 32 + c*8);
    }
    CPA_COMMIT();

    const int wm = w >> 1, wn = w & 1;
    float C[2][16][4];
#pragma unroll
    for (int mt = 0; mt < 2; mt++)
#pragma unroll
        for (int j = 0; j < 16; j++)
#pragma unroll
            for (int q = 0; q < 4; q++) C[mt][j][q] = 0.0f;

    const uint32_t krow = (uint32_t)((l & 7) + ((l >> 4) << 3));
    const uint32_t kcol = (uint32_t)(((l >> 3) & 1)) * 16;
    const uint32_t abase0 = (uint32_t)(32*wm + (l & 15))*APITCH + (uint32_t)(l >> 4)*16;
    const uint32_t abase1 = abase0 + 16*APITCH;

    for (int ch = 0; ch < 8; ch++) {
        CPA_WAIT1();
        __syncthreads();
        const uint32_t bbuf = sb + SBB + (uint32_t)(ch & 1)*40960;
#pragma unroll
        for (int kc2 = 0; kc2 < 2; kc2++) {
            const int kk = ch*2 + kc2;
            uint32_t Ah0[4], Al0[4], Ah1[4], Al1[4];
            ldsm4(Ah0, sb + SA_HI + abase0 + (uint32_t)kk*32);
            ldsm4(Al0, sb + SA_LO + abase0 + (uint32_t)kk*32);
            ldsm4(Ah1, sb + SA_HI + abase1 + (uint32_t)kk*32);
            ldsm4(Al1, sb + SA_LO + abase1 + (uint32_t)kk*32);
#pragma unroll
            for (int np = 0; np < 8; np++) {
                uint32_t Bh[4], Bl[4];
                uint32_t bo = (krow + (uint32_t)(wn*128 + np*16))*BPITCH + (uint32_t)kc2*32 + kcol;
                ldsm4(Bh, bbuf + bo);
                ldsm4(Bl, bbuf + 20480 + bo);
                mma16816(C[0][2*np],   Ah0, Bh);   mma16816(C[0][2*np],   Ah0, Bl);   mma16816(C[0][2*np],   Al0, Bh);
                mma16816(C[0][2*np+1], Ah0, Bh+2); mma16816(C[0][2*np+1], Ah0, Bl+2); mma16816(C[0][2*np+1], Al0, Bh+2);
                mma16816(C[1][2*np],   Ah1, Bh);   mma16816(C[1][2*np],   Ah1, Bl);   mma16816(C[1][2*np],   Al1, Bh);
                mma16816(C[1][2*np+1], Ah1, Bh+2); mma16816(C[1][2*np+1], Ah1, Bl+2); mma16816(C[1][2*np+1], Al1, Bh+2);
            }
        }
        __syncthreads();
        if (ch + 2 < 8) {
            const int k0 = (ch + 2)*32;
            const uint32_t dst = sb + SBB + (uint32_t)(ch & 1)*40960;
#pragma unroll
            for (int p = 0; p < 4; p++) {
                int idx = tid + p*256; int n = idx >> 2, c = idx & 3;
                cpa16(dst + (uint32_t)n*BPITCH + (uint32_t)c*16, wthi + n*H_ + k0 + c*8);
                cpa16(dst + 20480 + (uint32_t)n*BPITCH + (uint32_t)c*16, wtlo + n*H_ + k0 + c*8);
            }
        }
        CPA_COMMIT();
    }

    const int c0 = 2*(l & 3);
#pragma unroll
    for (int mt = 0; mt < 2; mt++) {
        const int r0 = row0 + 32*wm + 16*mt + (l >> 2);
#pragma unroll
        for (int jn = 0; jn < 16; jn++) {
            const int col = wn*128 + jn*8 + c0;
            const float b0 = 16.0f*bias[col], b1 = 16.0f*bias[col+1];
            float v0 = C[mt][jn][0] + b0, v1 = C[mt][jn][1] + b1;
            float v2 = C[mt][jn][2] + b0, v3 = C[mt][jn][3] + b1;
            __half h0 = __float2half(v0), h1 = __float2half(v1);
            __half h2 = __float2half(v2), h3 = __float2half(v3);
            *(uint32_t*)(ohi + (size_t)r0*H_ + col) =
                ((uint32_t)__half_as_ushort(h0)) | ((uint32_t)__half_as_ushort(h1) << 16);
            *(uint32_t*)(ohi + (size_t)(r0+8)*H_ + col) =
                ((uint32_t)__half_as_ushort(h2)) | ((uint32_t)__half_as_ushort(h3) << 16);
            if (z == 0) {
                *(uint32_t*)(g_qlo + (size_t)r0*H_ + col) =
                    packh2(v0 - __half2float(h0), v1 - __half2float(h1));
                *(uint32_t*)(g_qlo + (size_t)(r0+8)*H_ + col) =
                    packh2(v2 - __half2float(h2), v3 - __half2float(h3));
            }
        }
    }
}

// ---------------------------------------------------------------------------
// Kernel B: FA2-style mma.sync attention (Q split fp16x2; K,V,P plain fp16)
//           + cp.async pipeline (K prefetch overlaps softmax+PV) + LN + ReLU.
// ---------------------------------------------------------------------------
#define PITCH 528
#define SQHI  0
#define SQLO  67584
#define SK    135168
#define SV    168960
#define SMASK 202752
#define SGAM  202880
#define SBET  203904
#define SMEM_ATTN 204928

__global__ __launch_bounds__(256, 1)
void attn_mma_kernel(const int* __restrict__ masks,
                     const float* __restrict__ gamma,
                     const float* __restrict__ beta,
                     float* __restrict__ out)
{
    extern __shared__ char smc[];
    const uint32_t sb = smem_u32(smc);
    const int tid = threadIdx.x, w = tid >> 5, l = tid & 31;
    const int b = blockIdx.y, q0 = blockIdx.x * QT;

    const size_t kb0 = (size_t)(b*N_) * H_;

#pragma unroll
    for (int p = 0; p < 8; p++) {
        int idx = tid + p*256; int r = idx >> 5, c = idx & 31;
        cpa16(sb + SK + (uint32_t)r*PITCH + (uint32_t)c*16, g_khi + kb0 + (size_t)r*H_ + c*8);
    }
    CPA_COMMIT();
#pragma unroll
    for (int p = 0; p < 8; p++) {
        int idx = tid + p*256; int r = idx >> 5, c = idx & 31;
        cpa16(sb + SV + (uint32_t)r*PITCH + (uint32_t)c*16, g_vhi + kb0 + (size_t)r*H_ + c*8);
    }
    CPA_COMMIT();

    {
        const size_t qb = (size_t)(b*N_ + q0) * H_;
        for (int idx = tid; idx < QT*32; idx += 256) {
            int r = idx >> 5, c = idx & 31;
            uint32_t so = (uint32_t)r*PITCH + (uint32_t)c*16;
            *(uint4*)(smc + SQHI + so) = *(const uint4*)(g_qhi + qb + (size_t)r*H_ + c*8);
            *(uint4*)(smc + SQLO + so) = *(const uint4*)(g_qlo + qb + (size_t)r*H_ + c*8);
        }
        if (tid < 32) {
            uint32_t wbits = 0;
            for (int j = 0; j < 32; j++) wbits |= (masks[b*N_ + tid*32 + j] ? 1u : 0u) << j;
            ((uint32_t*)(smc + SMASK))[tid] = wbits;
        }
        for (int idx = tid; idx < H_; idx += 256) {
            ((float*)(smc + SGAM))[idx] = gamma[idx];
            ((float*)(smc + SBET))[idx] = beta[idx];
        }
    }

    const int r0 = 16*w + (l >> 2), r1 = r0 + 8;
    const bool mq0 = masks[b*N_ + q0 + r0] != 0, mq1 = masks[b*N_ + q0 + r1] != 0;

    float O[32][4];
#pragma unroll
    for (int t = 0; t < 32; t++)
#pragma unroll
        for (int j = 0; j < 4; j++) O[t][j] = 0.0f;
    float ls0 = 0.0f, ls1 = 0.0f;

    const int c0 = 2*(l & 3);
    const uint32_t aoff = (uint32_t)(16*w + (l & 15))*PITCH + (uint32_t)(l >> 4)*16;
    const uint32_t krow = (uint32_t)((l & 7) + ((l >> 4) << 3));
    const uint32_t kcol = (uint32_t)(((l >> 3) & 1))*16;
    const uint32_t vrow = (uint32_t)((l & 7) + (((l >> 3) & 1) << 3));
    const uint32_t vcol = (uint32_t)(l >> 4)*16;

    __syncthreads();

    for (int it = 0; it < 16; it++) {
        CPA_WAIT1();            // K_it arrived (V_it may still be in flight)
        __syncthreads();

        // ---- S = Q·K^T (16x64 per warp): Qhi·K + Qlo·K, dep-distance-2 ----
        float S[8][4];
#pragma unroll
        for (int t = 0; t < 8; t++)
#pragma unroll
            for (int j = 0; j < 4; j++) S[t][j] = 0.0f;

#pragma unroll 4
        for (int kc = 0; kc < 16; kc++) {
            uint32_t Ah[4], Al[4];
            uint32_t ao = aoff + (uint32_t)kc*32;
            ldsm4(Ah, sb + SQHI + ao);
            ldsm4(Al, sb + SQLO + ao);
#pragma unroll
            for (int np = 0; np < 4; np++) {
                uint32_t Bh[4];
                uint32_t ko = (krow + np*16)*PITCH + (uint32_t)kc*32 + kcol;
                ldsm4(Bh, sb + SK + ko);
                mma16816(S[2*np],   Ah, Bh);
                mma16816(S[2*np+1], Ah, Bh+2);
                mma16816(S[2*np],   Al, Bh);
                mma16816(S[2*np+1], Al, Bh+2);
            }
        }
        __syncthreads();        // all warps done reading K_it

        // ---- prefetch K_{it+1} NOW (overlaps softmax AND PV) ----
        if (it < 15) {
            const size_t kbn = (size_t)(b*N_ + (it+1)*64) * H_;
#pragma unroll
            for (int p = 0; p < 8; p++) {
                int idx = tid + p*256; int r = idx >> 5, c = idx & 31;
                cpa16(sb + SK + (uint32_t)r*PITCH + (uint32_t)c*16, g_khi + kbn + (size_t)r*H_ + c*8);
            }
        }
        CPA_COMMIT();

        // ---- softmax (reference-exact rounding) -> Phi fragments only ----
        const uint32_t w0 = ((uint32_t*)(smc + SMASK))[it*2];
        const uint32_t w1 = ((uint32_t*)(smc + SMASK))[it*2 + 1];
        uint32_t Phi[4][4];
#pragma unroll
        for (int j = 0; j < 8; j++) {
            int kidx = j*8 + c0;
            uint32_t mw = (j < 4) ? w0 : w1;
            int sh = kidx & 31;
            bool kb0m = (mw >> sh) & 1, kb1m = (mw >> (sh+1)) & 1;
            float p0 = softp(S[j][0], mq0, kb0m);
            float p1 = softp(S[j][1], mq0, kb1m);
            float p2 = softp(S[j][2], mq1, kb0m);
            float p3 = softp(S[j][3], mq1, kb1m);
            ls0 += p0 + p1; ls1 += p2 + p3;
            int kc = j >> 1, hi = (j & 1) ? 2 : 0;
            Phi[kc][hi+0] = packh2(p0, p1);
            Phi[kc][hi+1] = packh2(p2, p3);
        }

        CPA_WAIT1();            // V_it arrived (K_{it+1} may still be in flight)
        __syncthreads();

        // ---- O += P·V (16x256 per warp): Phi·V only ----
#pragma unroll
        for (int kc = 0; kc < 4; kc++) {
#pragma unroll
            for (int np = 0; np < 16; np++) {
                uint32_t Bh[4];
                uint32_t vo = (vrow + kc*16)*PITCH + (uint32_t)np*32 + vcol;
                ldsm4t(Bh, sb + SV + vo);
                mma16816(O[2*np],   Phi[kc], Bh);
                mma16816(O[2*np+1], Phi[kc], Bh+2);
            }
        }
        __syncthreads();        // all warps done reading V_it

        // ---- prefetch V_{it+1} (overlaps next S phase) ----
        if (it < 15) {
            const size_t vbn = (size_t)(b*N_ + (it+1)*64) * H_;
#pragma unroll
            for (int p = 0; p < 8; p++) {
                int idx = tid + p*256; int r = idx >> 5, c = idx & 31;
                cpa16(sb + SV + (uint32_t)r*PITCH + (uint32_t)c*16, g_vhi + vbn + (size_t)r*H_ + c*8);
            }
        }
        CPA_COMMIT();
    }

    // ---- epilogue: /l, LayerNorm (x16-invariant), ReLU, store ----
    ls0 += __shfl_xor_sync(0xffffffffu, ls0, 1); ls0 += __shfl_xor_sync(0xffffffffu, ls0, 2);
    ls1 += __shfl_xor_sync(0xffffffffu, ls1, 1); ls1 += __shfl_xor_sync(0xffffffffu, ls1, 2);
    const float inv0 = 1.0f / ls0, inv1 = 1.0f / ls1;

    float s0 = 0.0f, q0s = 0.0f, s1 = 0.0f, q1s = 0.0f;
#pragma unroll
    for (int t = 0; t < 32; t++) {
        float v0 = O[t][0]*inv0, v1 = O[t][1]*inv0;
        float v2 = O[t][2]*inv1, v3 = O[t][3]*inv1;
        s0 += v0 + v1; q0s = fmaf(v0,v0,fmaf(v1,v1,q0s));
        s1 += v2 + v3; q1s = fmaf(v2,v2,fmaf(v3,v3,q1s));
    }
    s0 += __shfl_xor_sync(0xffffffffu, s0, 1); s0 += __shfl_xor_sync(0xffffffffu, s0, 2);
    q0s += __shfl_xor_sync(0xffffffffu, q0s, 1); q0s += __shfl_xor_sync(0xffffffffu, q0s, 2);
    s1 += __shfl_xor_sync(0xffffffffu, s1, 1); s1 += __shfl_xor_sync(0xffffffffu, s1, 2);
    q1s += __shfl_xor_sync(0xffffffffu, q1s, 1); q1s += __shfl_xor_sync(0xffffffffu, q1s, 2);

    // (16o - 16mu)*rsqrt(256var + 256eps) = (o - mu)*rsqrt(var + eps)
    const float mu0 = s0 * (1.0f/H_), mu1 = s1 * (1.0f/H_);
    const float rstd0 = rsqrtf(fmaxf(q0s*(1.0f/H_) - mu0*mu0, 0.0f) + 1e-5f*256.0f);
    const float rstd1 = rsqrtf(fmaxf(q1s*(1.0f/H_) - mu1*mu1, 0.0f) + 1e-5f*256.0f);

    const float* gsm = (const float*)(smc + SGAM);
    const float* bsm = (const float*)(smc + SBET);
    const size_t ob0 = (size_t)(b*N_ + q0 + r0) * H_;
    const size_t ob1 = (size_t)(b*N_ + q0 + r1) * H_;
#pragma unroll
    for (int t = 0; t < 32; t++) {
        int col = t*8 + c0;
        float2 y0, y1;
        y0.x = fmaxf((O[t][0]*inv0 - mu0)*rstd0*gsm[col]   + bsm[col],   0.0f);
        y0.y = fmaxf((O[t][1]*inv0 - mu0)*rstd0*gsm[col+1] + bsm[col+1], 0.0f);
        y1.x = fmaxf((O[t][2]*inv1 - mu1)*rstd1*gsm[col]   + bsm[col],   0.0f);
        y1.y = fmaxf((O[t][3]*inv1 - mu1)*rstd1*gsm[col+1] + bsm[col+1], 0.0f);
        *(float2*)(out + ob0 + col) = y0;
        *(float2*)(out + ob1 + col) = y1;
    }
}

// ---------------------------------------------------------------------------
extern "C" void kernel_launch(void* const* d_in, const int* in_sizes, int n_in,
                              void* d_out, int out_size)
{
    const float* feats = (const float*)d_in[0];
    const int*   masks = (const int*)d_in[1];
    const float* Wq = (const float*)d_in[2];
    const float* bq = (const float*)d_in[3];
    const float* Wk = (const float*)d_in[4];
    const float* bk = (const float*)d_in[5];
    const float* Wv = (const float*)d_in[6];
    const float* bv = (const float*)d_in[7];
    const float* gamma = (const float*)d_in[8];
    const float* beta  = (const float*)d_in[9];
    float* out = (float*)d_out;

    split_feats_kernel<<<(B_*N_*H_)/(256*4), 256>>>(feats);
    split_w_kernel<<<dim3(H_, 3), 256>>>(Wq, Wk, Wv);

    cudaFuncSetAttribute(qkv_mma_kernel,
                         cudaFuncAttributeMaxDynamicSharedMemorySize,
                         SMEM_QKV);
    qkv_mma_kernel<<<dim3((B_*N_)/128, 1, 3), 256, SMEM_QKV>>>(bq, bk, bv);

    cudaFuncSetAttribute(attn_mma_kernel,
                         cudaFuncAttributeMaxDynamicSharedMemorySize,
                         SMEM_ATTN);
    dim3 gB(N_/QT, B_);
    attn_mma_kernel<<<gB, 256, SMEM_ATTN>>>(masks, gamma, beta, out);
}